// round 1
// baseline (speedup 1.0000x reference)
#include <cuda_runtime.h>

// Problem constants
#define BB 2
#define NSEQ 2048
#define DMODEL 512
#define NH 8
#define DHEAD 64
#define PCLAMP 64

// Scratch (device globals; no allocation allowed)
__device__ float g_q[BB * NH * NSEQ * DHEAD];
__device__ float g_k[BB * NH * NSEQ * DHEAD];
__device__ float g_v[BB * NH * NSEQ * DHEAD];
__device__ float g_ao[BB * NSEQ * DMODEL];

// ---------------------------------------------------------------------------
// Fused QKV projection: q/k/v = x @ W{q,k,v}; write in [b,h,n,d] layout.
// 64x64 output tile, K-step 16, 256 threads, 4x4 micro-tile per thread.
// ---------------------------------------------------------------------------
__global__ __launch_bounds__(256) void qkv_gemm(
    const float* __restrict__ x,
    const float* __restrict__ Wq,
    const float* __restrict__ Wk,
    const float* __restrict__ Wv)
{
    __shared__ float As[16][64];
    __shared__ float Bs[16][64];

    const float* W = (blockIdx.z == 0) ? Wq : (blockIdx.z == 1) ? Wk : Wv;
    float* out = (blockIdx.z == 0) ? g_q : (blockIdx.z == 1) ? g_k : g_v;

    const int m0 = blockIdx.y * 64;
    const int n0 = blockIdx.x * 64;
    const int tid = threadIdx.x;
    const int tm = tid >> 4;
    const int tn = tid & 15;

    float acc[4][4] = {};

    for (int k0 = 0; k0 < DMODEL; k0 += 16) {
        // A tile: 64 rows x 16 cols (k contiguous). 256 float4 loads.
        {
            int r = tid >> 2;
            int c = (tid & 3) * 4;
            float4 a = *(const float4*)&x[(m0 + r) * DMODEL + k0 + c];
            As[c + 0][r] = a.x;
            As[c + 1][r] = a.y;
            As[c + 2][r] = a.z;
            As[c + 3][r] = a.w;
            int rb = tid >> 4;
            int cb = (tid & 15) * 4;
            float4 b = *(const float4*)&W[(k0 + rb) * DMODEL + n0 + cb];
            *(float4*)&Bs[rb][cb] = b;
        }
        __syncthreads();
#pragma unroll
        for (int kk = 0; kk < 16; kk++) {
            float4 a4 = *(float4*)&As[kk][tm * 4];
            float4 b4 = *(float4*)&Bs[kk][tn * 4];
            float av[4] = {a4.x, a4.y, a4.z, a4.w};
            float bv[4] = {b4.x, b4.y, b4.z, b4.w};
#pragma unroll
            for (int i = 0; i < 4; i++)
#pragma unroll
                for (int j = 0; j < 4; j++)
                    acc[i][j] += av[i] * bv[j];
        }
        __syncthreads();
    }

#pragma unroll
    for (int i = 0; i < 4; i++) {
        int row = m0 + tm * 4 + i;
        int b = row >> 11;        // row / 2048
        int n = row & (NSEQ - 1); // row % 2048
#pragma unroll
        for (int j = 0; j < 4; j++) {
            int col = n0 + tn * 4 + j;
            int h = col >> 6;
            int d = col & 63;
            out[(((b * NH + h) * NSEQ) + n) * DHEAD + d] = acc[i][j];
        }
    }
}

// ---------------------------------------------------------------------------
// Flash attention with relative-position bias and post-softmax gate.
// One block per (query-tile of 64, head, batch). 256 threads.
// SMEM: qT[d][i] (16K) + kT[d][j] reused as pT[j][i] (16K) + vS[j][d] (16K).
// ---------------------------------------------------------------------------
__global__ __launch_bounds__(256) void attn_kernel(
    const float* __restrict__ rel_pos,
    const float* __restrict__ c_emb)
{
    __shared__ float qT[64][64];
    __shared__ float kT[64][64]; // also serves as pT[j][i] after scores
    __shared__ float vS[64][64];

    const int it = blockIdx.x;
    const int h  = blockIdx.y;
    const int b  = blockIdx.z;

    const float* qg = g_q + ((size_t)(b * NH + h) * NSEQ + it * 64) * DHEAD;
    const float* kg = g_k + ((size_t)(b * NH + h) * NSEQ) * DHEAD;
    const float* vg = g_v + ((size_t)(b * NH + h) * NSEQ) * DHEAD;

    const int tid = threadIdx.x;
    const int ti = tid >> 4;  // 0..15 : row group (4 rows)
    const int tj = tid & 15;  // 0..15 : col group (4 cols)

    // Load q tile transposed: qT[d][i]
#pragma unroll
    for (int rep = 0; rep < 4; rep++) {
        int li = tid + rep * 256;
        int r = li >> 4;
        int c = (li & 15) * 4;
        float4 a = *(const float4*)&qg[r * DHEAD + c];
        qT[c + 0][r] = a.x;
        qT[c + 1][r] = a.y;
        qT[c + 2][r] = a.z;
        qT[c + 3][r] = a.w;
    }

    float m_i[4], l_i[4], acc[4][4];
#pragma unroll
    for (int i = 0; i < 4; i++) {
        m_i[i] = -1e30f;
        l_i[i] = 0.f;
#pragma unroll
        for (int j = 0; j < 4; j++) acc[i][j] = 0.f;
    }

    const float scale = 0.125f; // DH^-0.5
    const int i_base = it * 64 + ti * 4;

    for (int jt = 0; jt < NSEQ / 64; jt++) {
        __syncthreads(); // previous AV reads done before overwriting kT/vS

        // Load k tile transposed kT[d][j] and v tile vS[j][d]
#pragma unroll
        for (int rep = 0; rep < 4; rep++) {
            int li = tid + rep * 256;
            int r = li >> 4;
            int c = (li & 15) * 4;
            float4 a = *(const float4*)&kg[(jt * 64 + r) * DHEAD + c];
            kT[c + 0][r] = a.x;
            kT[c + 1][r] = a.y;
            kT[c + 2][r] = a.z;
            kT[c + 3][r] = a.w;
            float4 vv = *(const float4*)&vg[(jt * 64 + r) * DHEAD + c];
            *(float4*)&vS[r][c] = vv;
        }
        __syncthreads();

        // Scores: s = q @ k^T   (64x64x64, GEMM-style)
        float s[4][4] = {};
#pragma unroll 8
        for (int d = 0; d < 64; d++) {
            float4 a4 = *(float4*)&qT[d][ti * 4];
            float4 b4 = *(float4*)&kT[d][tj * 4];
            float av[4] = {a4.x, a4.y, a4.z, a4.w};
            float bv[4] = {b4.x, b4.y, b4.z, b4.w};
#pragma unroll
            for (int i = 0; i < 4; i++)
#pragma unroll
                for (int j = 0; j < 4; j++)
                    s[i][j] += av[i] * bv[j];
        }

        // Bias + scale + row max
        float rmax[4];
#pragma unroll
        for (int ii = 0; ii < 4; ii++) {
            int i_g = i_base + ii;
            rmax[ii] = -1e30f;
#pragma unroll
            for (int jj = 0; jj < 4; jj++) {
                int j_g = jt * 64 + tj * 4 + jj;
                int rel = j_g - i_g;
                rel = min(max(rel, -PCLAMP), PCLAMP) + PCLAMP;
                float sv = (s[ii][jj] + __ldg(&rel_pos[rel * NH + h])) * scale;
                s[ii][jj] = sv;
                rmax[ii] = fmaxf(rmax[ii], sv);
            }
        }
#pragma unroll
        for (int ofs = 1; ofs < 16; ofs <<= 1)
#pragma unroll
            for (int ii = 0; ii < 4; ii++)
                rmax[ii] = fmaxf(rmax[ii], __shfl_xor_sync(0xffffffffu, rmax[ii], ofs));

        // Online softmax update
        float fac[4], rsum[4];
#pragma unroll
        for (int ii = 0; ii < 4; ii++) {
            float mn = fmaxf(m_i[ii], rmax[ii]);
            fac[ii] = __expf(m_i[ii] - mn);
            m_i[ii] = mn;
            rsum[ii] = 0.f;
#pragma unroll
            for (int jj = 0; jj < 4; jj++) {
                float p = __expf(s[ii][jj] - mn);
                s[ii][jj] = p;
                rsum[ii] += p;
            }
        }
#pragma unroll
        for (int ofs = 1; ofs < 16; ofs <<= 1)
#pragma unroll
            for (int ii = 0; ii < 4; ii++)
                rsum[ii] += __shfl_xor_sync(0xffffffffu, rsum[ii], ofs);
#pragma unroll
        for (int ii = 0; ii < 4; ii++) {
            l_i[ii] = l_i[ii] * fac[ii] + rsum[ii];
#pragma unroll
            for (int jj = 0; jj < 4; jj++) acc[ii][jj] *= fac[ii];
        }

        __syncthreads(); // all lanes finished reading kT (scores) before p write

        // Apply gate, write p into pT[j][i] (reusing kT buffer)
#pragma unroll
        for (int ii = 0; ii < 4; ii++) {
            int i_g = i_base + ii;
#pragma unroll
            for (int jj = 0; jj < 4; jj++) {
                int j_l = tj * 4 + jj;
                int j_g = jt * 64 + j_l;
                int rel = min(max(j_g - i_g, -PCLAMP), PCLAMP) + PCLAMP;
                kT[j_l][ti * 4 + ii] = s[ii][jj] * __ldg(&c_emb[rel * NH + h]);
            }
        }
        __syncthreads();

        // AV: acc[ii][dd] += pT[j][i] * vS[j][d]  (GEMM-style, d group = tj)
#pragma unroll 8
        for (int j = 0; j < 64; j++) {
            float4 p4 = *(float4*)&kT[j][ti * 4];
            float4 v4 = *(float4*)&vS[j][tj * 4];
            float pv[4] = {p4.x, p4.y, p4.z, p4.w};
            float vv[4] = {v4.x, v4.y, v4.z, v4.w};
#pragma unroll
            for (int ii = 0; ii < 4; ii++)
#pragma unroll
                for (int dd = 0; dd < 4; dd++)
                    acc[ii][dd] += pv[ii] * vv[dd];
        }
    }

    // Epilogue: normalize by l and store to [b, n, h*64+d] layout
    float* og = g_ao + ((size_t)(b * NSEQ + it * 64)) * DMODEL + h * DHEAD;
#pragma unroll
    for (int ii = 0; ii < 4; ii++) {
        float inv = 1.0f / l_i[ii];
        float4 o;
        o.x = acc[ii][0] * inv;
        o.y = acc[ii][1] * inv;
        o.z = acc[ii][2] * inv;
        o.w = acc[ii][3] * inv;
        *(float4*)&og[(ti * 4 + ii) * DMODEL + tj * 4] = o;
    }
}

// ---------------------------------------------------------------------------
// Output projection: out = attn_out @ Wo + bo
// ---------------------------------------------------------------------------
__global__ __launch_bounds__(256) void out_gemm(
    const float* __restrict__ Wo,
    const float* __restrict__ bo,
    float* __restrict__ Cout)
{
    __shared__ float As[16][64];
    __shared__ float Bs[16][64];

    const int m0 = blockIdx.y * 64;
    const int n0 = blockIdx.x * 64;
    const int tid = threadIdx.x;
    const int tm = tid >> 4;
    const int tn = tid & 15;

    float acc[4][4] = {};

    for (int k0 = 0; k0 < DMODEL; k0 += 16) {
        {
            int r = tid >> 2;
            int c = (tid & 3) * 4;
            float4 a = *(const float4*)&g_ao[(m0 + r) * DMODEL + k0 + c];
            As[c + 0][r] = a.x;
            As[c + 1][r] = a.y;
            As[c + 2][r] = a.z;
            As[c + 3][r] = a.w;
            int rb = tid >> 4;
            int cb = (tid & 15) * 4;
            float4 b = *(const float4*)&Wo[(k0 + rb) * DMODEL + n0 + cb];
            *(float4*)&Bs[rb][cb] = b;
        }
        __syncthreads();
#pragma unroll
        for (int kk = 0; kk < 16; kk++) {
            float4 a4 = *(float4*)&As[kk][tm * 4];
            float4 b4 = *(float4*)&Bs[kk][tn * 4];
            float av[4] = {a4.x, a4.y, a4.z, a4.w};
            float bv[4] = {b4.x, b4.y, b4.z, b4.w};
#pragma unroll
            for (int i = 0; i < 4; i++)
#pragma unroll
                for (int j = 0; j < 4; j++)
                    acc[i][j] += av[i] * bv[j];
        }
        __syncthreads();
    }

#pragma unroll
    for (int i = 0; i < 4; i++) {
        int row = m0 + tm * 4 + i;
#pragma unroll
        for (int j = 0; j < 4; j++) {
            int col = n0 + tn * 4 + j;
            Cout[row * DMODEL + col] = acc[i][j] + __ldg(&bo[col]);
        }
    }
}

// ---------------------------------------------------------------------------
// Launch
// ---------------------------------------------------------------------------
extern "C" void kernel_launch(void* const* d_in, const int* in_sizes, int n_in,
                              void* d_out, int out_size)
{
    const float* x       = (const float*)d_in[0];
    const float* Wq      = (const float*)d_in[1];
    const float* Wk      = (const float*)d_in[2];
    const float* Wv      = (const float*)d_in[3];
    const float* rel_pos = (const float*)d_in[4];
    const float* c_emb   = (const float*)d_in[5];
    const float* Wo      = (const float*)d_in[6];
    const float* bo      = (const float*)d_in[7];
    float* out = (float*)d_out;

    (void)in_sizes; (void)n_in; (void)out_size;

    dim3 g1(DMODEL / 64, (BB * NSEQ) / 64, 3);
    qkv_gemm<<<g1, 256>>>(x, Wq, Wk, Wv);

    dim3 g2(NSEQ / 64, NH, BB);
    attn_kernel<<<g2, 256>>>(rel_pos, c_emb);

    dim3 g3(DMODEL / 64, (BB * NSEQ) / 64, 1);
    out_gemm<<<g3, 256>>>(Wo, bo, out);
}

// round 2
// speedup vs baseline: 2.8784x; 2.8784x over previous
#include <cuda_runtime.h>

#define BB 2
#define NSEQ 2048
#define DMODEL 512
#define NH 8
#define DHEAD 64
#define PCLAMP 64

// Device-global scratch (no allocation allowed)
__device__ float g_q[BB * NH * NSEQ * DHEAD];
__device__ float g_k[BB * NH * NSEQ * DHEAD];
__device__ float g_v[BB * NH * NSEQ * DHEAD];
__device__ float g_ao[BB * NSEQ * DMODEL];

__device__ __forceinline__ unsigned f2tf32(float f) {
    unsigned r;
    asm("cvt.rna.tf32.f32 %0, %1;" : "=r"(r) : "f"(f));
    return r;
}

// D = A(16x8) * B(8x8) + D, tf32 inputs, f32 accum
__device__ __forceinline__ void mma8(float* c, const unsigned* a, const unsigned* b) {
    asm volatile(
        "mma.sync.aligned.m16n8k8.row.col.f32.tf32.tf32.f32 "
        "{%0,%1,%2,%3}, {%4,%5,%6,%7}, {%8,%9}, {%0,%1,%2,%3};"
        : "+f"(c[0]), "+f"(c[1]), "+f"(c[2]), "+f"(c[3])
        : "r"(a[0]), "r"(a[1]), "r"(a[2]), "r"(a[3]), "r"(b[0]), "r"(b[1]));
}

// ---------------------------------------------------------------------------
// TF32 GEMM: C[4096x512] = A[4096x512] @ W[512x512]
// MODE 0: A = x, W per blockIdx.z (Wq/Wk/Wv), output scattered to g_q/g_k/g_v
//         in [b,h,n,d] layout.
// MODE 1: A = g_ao, W = Wq arg (Wo), output = Cdirect + bias.
// Block: 256 thr (8 warps 4x2), tile 128x64, BK=32. Warp tile 32x32.
// ---------------------------------------------------------------------------
template <int MODE>
__global__ __launch_bounds__(256) void gemm_tf32(
    const float* __restrict__ X,
    const float* __restrict__ Wq,
    const float* __restrict__ Wk,
    const float* __restrict__ Wv,
    const float* __restrict__ bo,
    float* __restrict__ Cdirect)
{
    __shared__ __align__(16) unsigned As[128][40];  // [m][k], pad 8 -> conflict-free frag loads
    __shared__ __align__(16) unsigned Bs[32][72];   // [k][n], pad 8

    const float* A = (MODE == 0) ? X : g_ao;
    const float* W = (MODE == 0)
        ? (blockIdx.z == 0 ? Wq : blockIdx.z == 1 ? Wk : Wv)
        : Wq;

    const int m0 = blockIdx.y * 128;
    const int n0 = blockIdx.x * 64;
    const int tid = threadIdx.x;
    const int lane = tid & 31;
    const int wid = tid >> 5;
    const int gid = lane >> 2;  // 0..7
    const int tig = lane & 3;   // 0..3
    const int wm = (wid & 3) * 32;
    const int wn = (wid >> 2) * 32;

    float acc[2][4][4] = {};

    for (int k0 = 0; k0 < DMODEL; k0 += 32) {
#pragma unroll
        for (int i = 0; i < 4; i++) {
            int id = tid + i * 256;
            int r = id >> 3;
            int c = (id & 7) * 4;
            float4 a4 = *(const float4*)&A[(m0 + r) * DMODEL + k0 + c];
            uint4 u;
            u.x = f2tf32(a4.x); u.y = f2tf32(a4.y);
            u.z = f2tf32(a4.z); u.w = f2tf32(a4.w);
            *(uint4*)&As[r][c] = u;
        }
#pragma unroll
        for (int i = 0; i < 2; i++) {
            int id = tid + i * 256;
            int r = id >> 4;
            int c = (id & 15) * 4;
            float4 b4 = *(const float4*)&W[(k0 + r) * DMODEL + n0 + c];
            uint4 u;
            u.x = f2tf32(b4.x); u.y = f2tf32(b4.y);
            u.z = f2tf32(b4.z); u.w = f2tf32(b4.w);
            *(uint4*)&Bs[r][c] = u;
        }
        __syncthreads();

#pragma unroll
        for (int ks = 0; ks < 4; ks++) {
            unsigned a[2][4];
#pragma unroll
            for (int mf = 0; mf < 2; mf++) {
                int mb = wm + mf * 16 + gid;
                a[mf][0] = As[mb][ks * 8 + tig];
                a[mf][1] = As[mb + 8][ks * 8 + tig];
                a[mf][2] = As[mb][ks * 8 + tig + 4];
                a[mf][3] = As[mb + 8][ks * 8 + tig + 4];
            }
#pragma unroll
            for (int nf = 0; nf < 4; nf++) {
                unsigned b[2];
                b[0] = Bs[ks * 8 + tig][wn + nf * 8 + gid];
                b[1] = Bs[ks * 8 + tig + 4][wn + nf * 8 + gid];
                mma8(acc[0][nf], a[0], b);
                mma8(acc[1][nf], a[1], b);
            }
        }
        __syncthreads();
    }

    // Epilogue
#pragma unroll
    for (int mf = 0; mf < 2; mf++) {
#pragma unroll
        for (int nf = 0; nf < 4; nf++) {
            int row0 = m0 + wm + mf * 16 + gid;
            int row1 = row0 + 8;
            int col = n0 + wn + nf * 8 + 2 * tig;
            if (MODE == 0) {
                float* outp = blockIdx.z == 0 ? g_q : blockIdx.z == 1 ? g_k : g_v;
                int hh = col >> 6, dd = col & 63;
                {
                    int bN = row0 >> 11, nn = row0 & (NSEQ - 1);
                    float2 v = make_float2(acc[mf][nf][0], acc[mf][nf][1]);
                    *(float2*)&outp[((bN * NH + hh) * NSEQ + nn) * DHEAD + dd] = v;
                }
                {
                    int bN = row1 >> 11, nn = row1 & (NSEQ - 1);
                    float2 v = make_float2(acc[mf][nf][2], acc[mf][nf][3]);
                    *(float2*)&outp[((bN * NH + hh) * NSEQ + nn) * DHEAD + dd] = v;
                }
            } else {
                float2 bv = *(const float2*)&bo[col];
                float2 v0 = make_float2(acc[mf][nf][0] + bv.x, acc[mf][nf][1] + bv.y);
                float2 v1 = make_float2(acc[mf][nf][2] + bv.x, acc[mf][nf][3] + bv.y);
                *(float2*)&Cdirect[row0 * DMODEL + col] = v0;
                *(float2*)&Cdirect[row1 * DMODEL + col] = v1;
            }
        }
    }
}

// ---------------------------------------------------------------------------
// TF32 flash attention with relative-position bias + post-softmax gate.
// Block: 128 thr (4 warps), one (b, h, 64-query tile). Warp owns 16 rows.
// Q held in registers (pre-scaled); K buffer reused for gated P.
// ---------------------------------------------------------------------------
__global__ __launch_bounds__(128) void attn_tf32(
    const float* __restrict__ rel_pos,
    const float* __restrict__ c_emb)
{
    __shared__ __align__(16) unsigned KPs[64][72]; // K tile [j][d]; later P^T [j][i]
    __shared__ __align__(16) unsigned Vs[64][72];  // V tile [j][d]
    __shared__ float bias_s[132];
    __shared__ float gate_s[132];

    const int it = blockIdx.x;
    const int h  = blockIdx.y;
    const int b  = blockIdx.z;
    const int tid = threadIdx.x;
    const int lane = tid & 31;
    const int w = tid >> 5;       // warp 0..3
    const int gid = lane >> 2;    // 0..7
    const int tig = lane & 3;     // 0..3
    const int iloc = w * 16;
    const float scale = 0.125f;

    // Stage bias/gate LUTs (pre-scaled bias)
    for (int r = tid; r < 2 * PCLAMP + 1; r += 128) {
        bias_s[r] = __ldg(&rel_pos[r * NH + h]) * scale;
        gate_s[r] = __ldg(&c_emb[r * NH + h]);
    }

    // Q strip -> registers as tf32 A-fragments (scale folded in)
    const float* qg = g_q + ((size_t)(b * NH + h) * NSEQ + it * 64 + iloc) * DHEAD;
    unsigned qa[8][4];
#pragma unroll
    for (int ks = 0; ks < 8; ks++) {
        qa[ks][0] = f2tf32(__ldg(&qg[gid * DHEAD + ks * 8 + tig]) * scale);
        qa[ks][1] = f2tf32(__ldg(&qg[(gid + 8) * DHEAD + ks * 8 + tig]) * scale);
        qa[ks][2] = f2tf32(__ldg(&qg[gid * DHEAD + ks * 8 + tig + 4]) * scale);
        qa[ks][3] = f2tf32(__ldg(&qg[(gid + 8) * DHEAD + ks * 8 + tig + 4]) * scale);
    }

    const float* kg = g_k + ((size_t)(b * NH + h) * NSEQ) * DHEAD;
    const float* vg = g_v + ((size_t)(b * NH + h) * NSEQ) * DHEAD;

    float o[8][4] = {};
    float m0 = -1e30f, m1 = -1e30f, l0 = 0.f, l1 = 0.f;
    const int i0g = it * 64 + iloc + gid;   // row for c0/c1
    const int i1g = i0g + 8;                // row for c2/c3

    for (int jt = 0; jt < NSEQ / 64; jt++) {
        __syncthreads(); // prior tile's KPs/Vs fully consumed

        // Load K/V tile (tf32-converted), natural [j][d] layout
#pragma unroll
        for (int i = 0; i < 8; i++) {
            int id = tid + i * 128;
            int r = id >> 4;
            int c = (id & 15) * 4;
            float4 k4 = *(const float4*)&kg[(jt * 64 + r) * DHEAD + c];
            uint4 uk;
            uk.x = f2tf32(k4.x); uk.y = f2tf32(k4.y);
            uk.z = f2tf32(k4.z); uk.w = f2tf32(k4.w);
            *(uint4*)&KPs[r][c] = uk;
            float4 v4 = *(const float4*)&vg[(jt * 64 + r) * DHEAD + c];
            uint4 uv;
            uv.x = f2tf32(v4.x); uv.y = f2tf32(v4.y);
            uv.z = f2tf32(v4.z); uv.w = f2tf32(v4.w);
            *(uint4*)&Vs[r][c] = uv;
        }
        __syncthreads();

        // Scores: S_strip[16x64] = Qs @ K^T
        float s[8][4] = {};
#pragma unroll
        for (int ks = 0; ks < 8; ks++) {
#pragma unroll
            for (int nf = 0; nf < 8; nf++) {
                unsigned bfr[2];
                bfr[0] = KPs[nf * 8 + gid][ks * 8 + tig];
                bfr[1] = KPs[nf * 8 + gid][ks * 8 + tig + 4];
                mma8(s[nf], qa[ks], bfr);
            }
        }
        __syncthreads(); // all warps done reading K before P overwrite

        // Bias + row max
        float rmax0 = -1e30f, rmax1 = -1e30f;
#pragma unroll
        for (int nf = 0; nf < 8; nf++) {
            int jb = jt * 64 + nf * 8 + 2 * tig;
            int d00 = min(max(jb - i0g, -PCLAMP), PCLAMP) + PCLAMP;
            int d01 = min(max(jb + 1 - i0g, -PCLAMP), PCLAMP) + PCLAMP;
            int d10 = min(max(jb - i1g, -PCLAMP), PCLAMP) + PCLAMP;
            int d11 = min(max(jb + 1 - i1g, -PCLAMP), PCLAMP) + PCLAMP;
            s[nf][0] += bias_s[d00];
            s[nf][1] += bias_s[d01];
            s[nf][2] += bias_s[d10];
            s[nf][3] += bias_s[d11];
            rmax0 = fmaxf(rmax0, fmaxf(s[nf][0], s[nf][1]));
            rmax1 = fmaxf(rmax1, fmaxf(s[nf][2], s[nf][3]));
        }
#pragma unroll
        for (int ofs = 1; ofs < 4; ofs <<= 1) {
            rmax0 = fmaxf(rmax0, __shfl_xor_sync(0xffffffffu, rmax0, ofs));
            rmax1 = fmaxf(rmax1, __shfl_xor_sync(0xffffffffu, rmax1, ofs));
        }

        // Online softmax update
        float mn0 = fmaxf(m0, rmax0), mn1 = fmaxf(m1, rmax1);
        float f0 = __expf(m0 - mn0), f1 = __expf(m1 - mn1);
        m0 = mn0; m1 = mn1;
        float rs0 = 0.f, rs1 = 0.f;
#pragma unroll
        for (int nf = 0; nf < 8; nf++) {
            s[nf][0] = __expf(s[nf][0] - mn0);
            s[nf][1] = __expf(s[nf][1] - mn0);
            s[nf][2] = __expf(s[nf][2] - mn1);
            s[nf][3] = __expf(s[nf][3] - mn1);
            rs0 += s[nf][0] + s[nf][1];
            rs1 += s[nf][2] + s[nf][3];
        }
#pragma unroll
        for (int ofs = 1; ofs < 4; ofs <<= 1) {
            rs0 += __shfl_xor_sync(0xffffffffu, rs0, ofs);
            rs1 += __shfl_xor_sync(0xffffffffu, rs1, ofs);
        }
        l0 = l0 * f0 + rs0;
        l1 = l1 * f1 + rs1;
#pragma unroll
        for (int nf = 0; nf < 8; nf++) {
            o[nf][0] *= f0; o[nf][1] *= f0;
            o[nf][2] *= f1; o[nf][3] *= f1;
        }

        // Gated P -> KPs as P^T [j][i] (warp-private columns)
#pragma unroll
        for (int nf = 0; nf < 8; nf++) {
            int jl = nf * 8 + 2 * tig;
            int jb = jt * 64 + jl;
            int d00 = min(max(jb - i0g, -PCLAMP), PCLAMP) + PCLAMP;
            int d01 = min(max(jb + 1 - i0g, -PCLAMP), PCLAMP) + PCLAMP;
            int d10 = min(max(jb - i1g, -PCLAMP), PCLAMP) + PCLAMP;
            int d11 = min(max(jb + 1 - i1g, -PCLAMP), PCLAMP) + PCLAMP;
            KPs[jl][iloc + gid]         = f2tf32(s[nf][0] * gate_s[d00]);
            KPs[jl + 1][iloc + gid]     = f2tf32(s[nf][1] * gate_s[d01]);
            KPs[jl][iloc + gid + 8]     = f2tf32(s[nf][2] * gate_s[d10]);
            KPs[jl + 1][iloc + gid + 8] = f2tf32(s[nf][3] * gate_s[d11]);
        }
        __syncwarp();

        // O += P @ V
#pragma unroll
        for (int ks = 0; ks < 8; ks++) {
            unsigned a[4];
            a[0] = KPs[ks * 8 + tig][iloc + gid];
            a[1] = KPs[ks * 8 + tig][iloc + gid + 8];
            a[2] = KPs[ks * 8 + tig + 4][iloc + gid];
            a[3] = KPs[ks * 8 + tig + 4][iloc + gid + 8];
#pragma unroll
            for (int nf = 0; nf < 8; nf++) {
                unsigned bfr[2];
                bfr[0] = Vs[ks * 8 + tig][nf * 8 + gid];
                bfr[1] = Vs[ks * 8 + tig + 4][nf * 8 + gid];
                mma8(o[nf], a, bfr);
            }
        }
    }

    // Epilogue: normalize, write [b, n, h*64+d]
    float inv0 = 1.0f / l0, inv1 = 1.0f / l1;
    float* og = g_ao + ((size_t)(b * NSEQ + it * 64 + iloc)) * DMODEL + h * DHEAD;
#pragma unroll
    for (int nf = 0; nf < 8; nf++) {
        int col = nf * 8 + 2 * tig;
        *(float2*)&og[gid * DMODEL + col] =
            make_float2(o[nf][0] * inv0, o[nf][1] * inv0);
        *(float2*)&og[(gid + 8) * DMODEL + col] =
            make_float2(o[nf][2] * inv1, o[nf][3] * inv1);
    }
}

// ---------------------------------------------------------------------------
// Launch
// ---------------------------------------------------------------------------
extern "C" void kernel_launch(void* const* d_in, const int* in_sizes, int n_in,
                              void* d_out, int out_size)
{
    const float* x       = (const float*)d_in[0];
    const float* Wq      = (const float*)d_in[1];
    const float* Wk      = (const float*)d_in[2];
    const float* Wv      = (const float*)d_in[3];
    const float* rel_pos = (const float*)d_in[4];
    const float* c_emb   = (const float*)d_in[5];
    const float* Wo      = (const float*)d_in[6];
    const float* bo      = (const float*)d_in[7];
    float* out = (float*)d_out;

    (void)in_sizes; (void)n_in; (void)out_size;

    dim3 gq(DMODEL / 64, (BB * NSEQ) / 128, 3);
    gemm_tf32<0><<<gq, 256>>>(x, Wq, Wk, Wv, nullptr, nullptr);

    dim3 ga(NSEQ / 64, NH, BB);
    attn_tf32<<<ga, 128>>>(rel_pos, c_emb);

    dim3 go(DMODEL / 64, (BB * NSEQ) / 128, 1);
    gemm_tf32<1><<<go, 256>>>(nullptr, Wo, nullptr, nullptr, bo, out);
}

// round 5
// speedup vs baseline: 6.2634x; 2.1760x over previous
#include <cuda_runtime.h>
#include <cuda_fp16.h>
#include <cstdint>

#define BB 2
#define NSEQ 2048
#define DMODEL 512
#define NH 8
#define DHEAD 64
#define PCLAMP 64

// Device-global scratch (no allocation allowed)
__device__ __half g_xh[BB * NSEQ * DMODEL];          // x in fp16
__device__ __half g_wh[4 * DMODEL * DMODEL];         // Wq,Wk,Wv,Wo in fp16
__device__ __half g_q[BB * NH * NSEQ * DHEAD];
__device__ __half g_k[BB * NH * NSEQ * DHEAD];
__device__ __half g_v[BB * NH * NSEQ * DHEAD];
__device__ __half g_aoh[BB * NSEQ * DMODEL];

__device__ __forceinline__ unsigned smem_u32(const void* p) {
    return (unsigned)__cvta_generic_to_shared(p);
}

__device__ __forceinline__ void ldsm4(unsigned& r0, unsigned& r1, unsigned& r2,
                                      unsigned& r3, unsigned addr) {
    asm volatile("ldmatrix.sync.aligned.m8n8.x4.shared.b16 {%0,%1,%2,%3}, [%4];"
                 : "=r"(r0), "=r"(r1), "=r"(r2), "=r"(r3) : "r"(addr));
}
__device__ __forceinline__ void ldsm4t(unsigned& r0, unsigned& r1, unsigned& r2,
                                       unsigned& r3, unsigned addr) {
    asm volatile("ldmatrix.sync.aligned.m8n8.x4.trans.shared.b16 {%0,%1,%2,%3}, [%4];"
                 : "=r"(r0), "=r"(r1), "=r"(r2), "=r"(r3) : "r"(addr));
}

// D(16x8,f32) += A(16x16,f16) * B(16x8,f16)
__device__ __forceinline__ void mma16(float* c, const unsigned* a, const unsigned* b) {
    asm volatile(
        "mma.sync.aligned.m16n8k16.row.col.f32.f16.f16.f32 "
        "{%0,%1,%2,%3}, {%4,%5,%6,%7}, {%8,%9}, {%0,%1,%2,%3};"
        : "+f"(c[0]), "+f"(c[1]), "+f"(c[2]), "+f"(c[3])
        : "r"(a[0]), "r"(a[1]), "r"(a[2]), "r"(a[3]), "r"(b[0]), "r"(b[1]));
}

__device__ __forceinline__ unsigned packh2(float lo, float hi) {
    __half2 h = __floats2half2_rn(lo, hi);
    return *(unsigned*)&h;
}

// ---------------------------------------------------------------------------
// fp32 -> fp16 conversion of x and all 4 weight matrices.
// 786432 float4s total: x = 524288, each W = 65536.
// ---------------------------------------------------------------------------
__global__ __launch_bounds__(256) void cvt_kernel(
    const float* __restrict__ x, const float* __restrict__ Wq,
    const float* __restrict__ Wk, const float* __restrict__ Wv,
    const float* __restrict__ Wo)
{
    int i = blockIdx.x * 256 + threadIdx.x;
#pragma unroll
    for (int t = 0; t < 4; t++, i += 196608) {
        const float* src;
        __half* dst;
        int off;
        if (i < 524288) { src = x; dst = g_xh; off = i; }
        else {
            int j = i - 524288;
            int w = j >> 16;
            off = j & 65535;
            src = (w == 0) ? Wq : (w == 1) ? Wk : (w == 2) ? Wv : Wo;
            dst = g_wh + w * (DMODEL * DMODEL);
        }
        float4 v = ((const float4*)src)[off];
        unsigned lo = packh2(v.x, v.y);
        unsigned hi = packh2(v.z, v.w);
        *(uint2*)&dst[off * 4] = make_uint2(lo, hi);
    }
}

// ---------------------------------------------------------------------------
// fp16 GEMM: C[4096x512] = A[4096x512] @ W[512x512]
// MODE 0: A = g_xh, W per blockIdx.z -> g_q/g_k/g_v ([b,h,n,d], fp16)
// MODE 1: A = g_aoh, W = Wo -> f32 out + bias
// Block 256 thr (8 warps 4x2), tile 128x64, BK=32, warp tile 32x32.
// ---------------------------------------------------------------------------
template <int MODE>
__global__ __launch_bounds__(256) void gemm_h(
    const float* __restrict__ bo, float* __restrict__ Cout)
{
    __shared__ __align__(16) __half As[128][40];  // pitch 80B: conflict-free LDSM
    __shared__ __align__(16) __half Bs[32][72];   // pitch 144B

    const __half* A = (MODE == 0) ? g_xh : g_aoh;
    const __half* W = (MODE == 0) ? g_wh + blockIdx.z * (DMODEL * DMODEL)
                                  : g_wh + 3 * (DMODEL * DMODEL);

    const int m0 = blockIdx.y * 128;
    const int n0 = blockIdx.x * 64;
    const int tid = threadIdx.x;
    const int lane = tid & 31;
    const int wid = tid >> 5;
    const int gid = lane >> 2;
    const int tig = lane & 3;
    const int wm = (wid & 3) * 32;
    const int wn = (wid >> 2) * 32;

    float acc[2][4][4] = {};

    for (int k0 = 0; k0 < DMODEL; k0 += 32) {
        // A tile 128x32 (two 16B vec loads/thread)
#pragma unroll
        for (int i = 0; i < 2; i++) {
            int id = tid + i * 256;
            int r = id >> 2;
            int c = (id & 3) * 8;
            *(uint4*)&As[r][c] = *(const uint4*)&A[(m0 + r) * DMODEL + k0 + c];
        }
        // B tile 32x64 (one 16B vec load/thread)
        {
            int r = tid >> 3;
            int c = (tid & 7) * 8;
            *(uint4*)&Bs[r][c] = *(const uint4*)&W[(k0 + r) * DMODEL + n0 + c];
        }
        __syncthreads();

#pragma unroll
        for (int kc = 0; kc < 2; kc++) {
            unsigned a[2][4];
#pragma unroll
            for (int mf = 0; mf < 2; mf++) {
                unsigned addr = smem_u32(&As[wm + mf * 16 + (lane & 15)]
                                            [kc * 16 + (lane >> 4) * 8]);
                ldsm4(a[mf][0], a[mf][1], a[mf][2], a[mf][3], addr);
            }
#pragma unroll
            for (int nf2 = 0; nf2 < 2; nf2++) {
                unsigned b[4];
                unsigned addr = smem_u32(&Bs[kc * 16 + (lane & 15)]
                                            [wn + nf2 * 16 + (lane >> 4) * 8]);
                ldsm4t(b[0], b[1], b[2], b[3], addr);
                int nf = nf2 * 2;
                mma16(acc[0][nf], a[0], b + 0);
                mma16(acc[1][nf], a[1], b + 0);
                mma16(acc[0][nf + 1], a[0], b + 2);
                mma16(acc[1][nf + 1], a[1], b + 2);
            }
        }
        __syncthreads();
    }

    // Epilogue
#pragma unroll
    for (int mf = 0; mf < 2; mf++) {
#pragma unroll
        for (int nf = 0; nf < 4; nf++) {
            int row0 = m0 + wm + mf * 16 + gid;
            int row1 = row0 + 8;
            int col = n0 + wn + nf * 8 + 2 * tig;
            if (MODE == 0) {
                __half* outp = (blockIdx.z == 0) ? g_q : (blockIdx.z == 1) ? g_k : g_v;
                int hh = col >> 6, dd = col & 63;
                {
                    int bN = row0 >> 11, nn = row0 & (NSEQ - 1);
                    *(unsigned*)&outp[((bN * NH + hh) * NSEQ + nn) * DHEAD + dd] =
                        packh2(acc[mf][nf][0], acc[mf][nf][1]);
                }
                {
                    int bN = row1 >> 11, nn = row1 & (NSEQ - 1);
                    *(unsigned*)&outp[((bN * NH + hh) * NSEQ + nn) * DHEAD + dd] =
                        packh2(acc[mf][nf][2], acc[mf][nf][3]);
                }
            } else {
                float2 bv = *(const float2*)&bo[col];
                *(float2*)&Cout[row0 * DMODEL + col] =
                    make_float2(acc[mf][nf][0] + bv.x, acc[mf][nf][1] + bv.y);
                *(float2*)&Cout[row1 * DMODEL + col] =
                    make_float2(acc[mf][nf][2] + bv.x, acc[mf][nf][3] + bv.y);
            }
        }
    }
}

// ---------------------------------------------------------------------------
// fp16 flash attention, rel-pos bias + post-softmax gate.
// Block 128 thr (4 warps), one (b,h,64-row q tile). Warp owns 16 rows.
// Q fragments in registers (scale folded). P converts C->A frags in registers.
// ---------------------------------------------------------------------------
__global__ __launch_bounds__(128) void attn_h(
    const float* __restrict__ rel_pos, const float* __restrict__ c_emb)
{
    __shared__ __align__(16) __half Ks[64][72];  // [j][d], pitch 144B
    __shared__ __align__(16) __half Vs[64][72];
    __shared__ float bias_s[132];
    __shared__ float gate_s[132];

    const int it = blockIdx.x;
    const int h  = blockIdx.y;
    const int b  = blockIdx.z;
    const int tid = threadIdx.x;
    const int lane = tid & 31;
    const int w = tid >> 5;
    const int gid = lane >> 2;
    const int tig = lane & 3;
    const int iloc = w * 16;

    for (int r = tid; r < 2 * PCLAMP + 1; r += 128) {
        bias_s[r] = __ldg(&rel_pos[r * NH + h]) * 0.125f;
        gate_s[r] = __ldg(&c_emb[r * NH + h]);
    }

    // Q strip -> A fragments, scale 0.125 folded (exact in fp16)
    const __half* qg = g_q + ((size_t)(b * NH + h) * NSEQ + it * 64 + iloc) * DHEAD;
    const __half2 sc = __float2half2_rn(0.125f);
    unsigned qa[4][4];
#pragma unroll
    for (int kc = 0; kc < 4; kc++) {
        __half2 v0 = *(const __half2*)&qg[gid * DHEAD + kc * 16 + 2 * tig];
        __half2 v1 = *(const __half2*)&qg[(gid + 8) * DHEAD + kc * 16 + 2 * tig];
        __half2 v2 = *(const __half2*)&qg[gid * DHEAD + kc * 16 + 8 + 2 * tig];
        __half2 v3 = *(const __half2*)&qg[(gid + 8) * DHEAD + kc * 16 + 8 + 2 * tig];
        v0 = __hmul2(v0, sc); v1 = __hmul2(v1, sc);
        v2 = __hmul2(v2, sc); v3 = __hmul2(v3, sc);
        qa[kc][0] = *(unsigned*)&v0; qa[kc][1] = *(unsigned*)&v1;
        qa[kc][2] = *(unsigned*)&v2; qa[kc][3] = *(unsigned*)&v3;
    }

    const __half* kg = g_k + ((size_t)(b * NH + h) * NSEQ) * DHEAD;
    const __half* vg = g_v + ((size_t)(b * NH + h) * NSEQ) * DHEAD;

    float o[8][4] = {};
    float m0 = -1e30f, m1 = -1e30f, l0 = 0.f, l1 = 0.f;
    const int i0g = it * 64 + iloc + gid;
    const int i1g = i0g + 8;

    for (int jt = 0; jt < NSEQ / 64; jt++) {
        __syncthreads();  // previous tile fully consumed
#pragma unroll
        for (int i = 0; i < 4; i++) {
            int id = tid + i * 128;
            int r = id >> 3;
            int c = (id & 7) * 8;
            *(uint4*)&Ks[r][c] = *(const uint4*)&kg[(jt * 64 + r) * DHEAD + c];
            *(uint4*)&Vs[r][c] = *(const uint4*)&vg[(jt * 64 + r) * DHEAD + c];
        }
        __syncthreads();

        // S = Qs @ K^T  (16x64 strip per warp)
        float s[8][4] = {};
#pragma unroll
        for (int kc = 0; kc < 4; kc++) {
#pragma unroll
            for (int nf2 = 0; nf2 < 4; nf2++) {
                unsigned bfr[4];
                unsigned addr = smem_u32(
                    &Ks[nf2 * 16 + ((lane >> 4) & 1) * 8 + (lane & 7)]
                       [kc * 16 + ((lane >> 3) & 1) * 8]);
                ldsm4(bfr[0], bfr[1], bfr[2], bfr[3], addr);
                mma16(s[nf2 * 2], qa[kc], bfr + 0);
                mma16(s[nf2 * 2 + 1], qa[kc], bfr + 2);
            }
        }

        // Bias + row max
        float rmax0 = -1e30f, rmax1 = -1e30f;
#pragma unroll
        for (int nf = 0; nf < 8; nf++) {
            int jb = jt * 64 + nf * 8 + 2 * tig;
            int d00 = min(max(jb - i0g, -PCLAMP), PCLAMP) + PCLAMP;
            int d01 = min(max(jb + 1 - i0g, -PCLAMP), PCLAMP) + PCLAMP;
            int d10 = min(max(jb - i1g, -PCLAMP), PCLAMP) + PCLAMP;
            int d11 = min(max(jb + 1 - i1g, -PCLAMP), PCLAMP) + PCLAMP;
            s[nf][0] += bias_s[d00];
            s[nf][1] += bias_s[d01];
            s[nf][2] += bias_s[d10];
            s[nf][3] += bias_s[d11];
            rmax0 = fmaxf(rmax0, fmaxf(s[nf][0], s[nf][1]));
            rmax1 = fmaxf(rmax1, fmaxf(s[nf][2], s[nf][3]));
        }
#pragma unroll
        for (int ofs = 1; ofs < 4; ofs <<= 1) {
            rmax0 = fmaxf(rmax0, __shfl_xor_sync(0xffffffffu, rmax0, ofs));
            rmax1 = fmaxf(rmax1, __shfl_xor_sync(0xffffffffu, rmax1, ofs));
        }

        float mn0 = fmaxf(m0, rmax0), mn1 = fmaxf(m1, rmax1);
        float f0 = __expf(m0 - mn0), f1 = __expf(m1 - mn1);
        m0 = mn0; m1 = mn1;
        float rs0 = 0.f, rs1 = 0.f;
#pragma unroll
        for (int nf = 0; nf < 8; nf++) {
            s[nf][0] = __expf(s[nf][0] - mn0);
            s[nf][1] = __expf(s[nf][1] - mn0);
            s[nf][2] = __expf(s[nf][2] - mn1);
            s[nf][3] = __expf(s[nf][3] - mn1);
            rs0 += s[nf][0] + s[nf][1];
            rs1 += s[nf][2] + s[nf][3];
        }
#pragma unroll
        for (int ofs = 1; ofs < 4; ofs <<= 1) {
            rs0 += __shfl_xor_sync(0xffffffffu, rs0, ofs);
            rs1 += __shfl_xor_sync(0xffffffffu, rs1, ofs);
        }
        l0 = l0 * f0 + rs0;
        l1 = l1 * f1 + rs1;
#pragma unroll
        for (int nf = 0; nf < 8; nf++) {
            o[nf][0] *= f0; o[nf][1] *= f0;
            o[nf][2] *= f1; o[nf][3] *= f1;
        }

        // Gate (in registers), then P C-frags -> A-frags, O += P @ V
#pragma unroll
        for (int nf = 0; nf < 8; nf++) {
            int jb = jt * 64 + nf * 8 + 2 * tig;
            int d00 = min(max(jb - i0g, -PCLAMP), PCLAMP) + PCLAMP;
            int d01 = min(max(jb + 1 - i0g, -PCLAMP), PCLAMP) + PCLAMP;
            int d10 = min(max(jb - i1g, -PCLAMP), PCLAMP) + PCLAMP;
            int d11 = min(max(jb + 1 - i1g, -PCLAMP), PCLAMP) + PCLAMP;
            s[nf][0] *= gate_s[d00];
            s[nf][1] *= gate_s[d01];
            s[nf][2] *= gate_s[d10];
            s[nf][3] *= gate_s[d11];
        }
#pragma unroll
        for (int kc2 = 0; kc2 < 4; kc2++) {
            unsigned a[4];
            a[0] = packh2(s[2 * kc2][0], s[2 * kc2][1]);
            a[1] = packh2(s[2 * kc2][2], s[2 * kc2][3]);
            a[2] = packh2(s[2 * kc2 + 1][0], s[2 * kc2 + 1][1]);
            a[3] = packh2(s[2 * kc2 + 1][2], s[2 * kc2 + 1][3]);
#pragma unroll
            for (int nf2 = 0; nf2 < 4; nf2++) {
                unsigned bfr[4];
                unsigned addr = smem_u32(&Vs[kc2 * 16 + (lane & 15)]
                                            [nf2 * 16 + (lane >> 4) * 8]);
                ldsm4t(bfr[0], bfr[1], bfr[2], bfr[3], addr);
                mma16(o[nf2 * 2], a, bfr + 0);
                mma16(o[nf2 * 2 + 1], a, bfr + 2);
            }
        }
    }

    // Epilogue: normalize, write fp16 [b, n, h*64+d]
    float inv0 = 1.0f / l0, inv1 = 1.0f / l1;
    __half* og = g_aoh + ((size_t)(b * NSEQ + it * 64 + iloc)) * DMODEL + h * DHEAD;
#pragma unroll
    for (int nf = 0; nf < 8; nf++) {
        int col = nf * 8 + 2 * tig;
        *(unsigned*)&og[gid * DMODEL + col] = packh2(o[nf][0] * inv0, o[nf][1] * inv0);
        *(unsigned*)&og[(gid + 8) * DMODEL + col] = packh2(o[nf][2] * inv1, o[nf][3] * inv1);
    }
}

// ---------------------------------------------------------------------------
// Launch
// ---------------------------------------------------------------------------
extern "C" void kernel_launch(void* const* d_in, const int* in_sizes, int n_in,
                              void* d_out, int out_size)
{
    const float* x       = (const float*)d_in[0];
    const float* Wq      = (const float*)d_in[1];
    const float* Wk      = (const float*)d_in[2];
    const float* Wv      = (const float*)d_in[3];
    const float* rel_pos = (const float*)d_in[4];
    const float* c_emb   = (const float*)d_in[5];
    const float* Wo      = (const float*)d_in[6];
    const float* bo      = (const float*)d_in[7];
    float* out = (float*)d_out;

    (void)in_sizes; (void)n_in; (void)out_size;

    cvt_kernel<<<768, 256>>>(x, Wq, Wk, Wv, Wo);

    dim3 gq(DMODEL / 64, (BB * NSEQ) / 128, 3);
    gemm_h<0><<<gq, 256>>>(nullptr, nullptr);

    dim3 ga(NSEQ / 64, NH, BB);
    attn_h<<<ga, 128>>>(rel_pos, c_emb);

    dim3 go(DMODEL / 64, (BB * NSEQ) / 128, 1);
    gemm_h<1><<<go, 256>>>(bo, out);
}

// round 9
// speedup vs baseline: 7.3780x; 1.1780x over previous
#include <cuda_runtime.h>
#include <cuda_fp16.h>
#include <cstdint>

#define BB 2
#define NSEQ 2048
#define DMODEL 512
#define NH 8
#define DHEAD 64
#define PCLAMP 64

// Device-global scratch (no allocation allowed)
__device__ __half g_xh[BB * NSEQ * DMODEL];
__device__ __half g_wh[4 * DMODEL * DMODEL];
__device__ __half g_q[BB * NH * NSEQ * DHEAD];
__device__ __half g_k[BB * NH * NSEQ * DHEAD];
__device__ __half g_v[BB * NH * NSEQ * DHEAD];
__device__ __half g_aoh[BB * NSEQ * DMODEL];

__device__ __forceinline__ unsigned smem_u32(const void* p) {
    return (unsigned)__cvta_generic_to_shared(p);
}
__device__ __forceinline__ void ldsm4(unsigned& r0, unsigned& r1, unsigned& r2,
                                      unsigned& r3, unsigned addr) {
    asm volatile("ldmatrix.sync.aligned.m8n8.x4.shared.b16 {%0,%1,%2,%3}, [%4];"
                 : "=r"(r0), "=r"(r1), "=r"(r2), "=r"(r3) : "r"(addr));
}
__device__ __forceinline__ void ldsm4t(unsigned& r0, unsigned& r1, unsigned& r2,
                                       unsigned& r3, unsigned addr) {
    asm volatile("ldmatrix.sync.aligned.m8n8.x4.trans.shared.b16 {%0,%1,%2,%3}, [%4];"
                 : "=r"(r0), "=r"(r1), "=r"(r2), "=r"(r3) : "r"(addr));
}
__device__ __forceinline__ void mma16(float* c, const unsigned* a, const unsigned* b) {
    asm volatile(
        "mma.sync.aligned.m16n8k16.row.col.f32.f16.f16.f32 "
        "{%0,%1,%2,%3}, {%4,%5,%6,%7}, {%8,%9}, {%0,%1,%2,%3};"
        : "+f"(c[0]), "+f"(c[1]), "+f"(c[2]), "+f"(c[3])
        : "r"(a[0]), "r"(a[1]), "r"(a[2]), "r"(a[3]), "r"(b[0]), "r"(b[1]));
}
__device__ __forceinline__ unsigned packh2(float lo, float hi) {
    __half2 h = __floats2half2_rn(lo, hi);
    return *(unsigned*)&h;
}

// ---------------------------------------------------------------------------
// fp32 -> fp16 conversion of x and 4 weight matrices.
// ---------------------------------------------------------------------------
__global__ __launch_bounds__(256) void cvt_kernel(
    const float* __restrict__ x, const float* __restrict__ Wq,
    const float* __restrict__ Wk, const float* __restrict__ Wv,
    const float* __restrict__ Wo)
{
    int i = blockIdx.x * 256 + threadIdx.x;
#pragma unroll
    for (int t = 0; t < 4; t++, i += 196608) {
        const float* src;
        __half* dst;
        int off;
        if (i < 524288) { src = x; dst = g_xh; off = i; }
        else {
            int j = i - 524288;
            int w = j >> 16;
            off = j & 65535;
            src = (w == 0) ? Wq : (w == 1) ? Wk : (w == 2) ? Wv : Wo;
            dst = g_wh + w * (DMODEL * DMODEL);
        }
        float4 v = ((const float4*)src)[off];
        *(uint2*)&dst[off * 4] = make_uint2(packh2(v.x, v.y), packh2(v.z, v.w));
    }
}

// ---------------------------------------------------------------------------
// fp16 GEMM: C[4096x512] = A[4096x512] @ W[512x512]
// Tile 128x128, BK=32, 256 thr (8 warps 2x4, warp tile 64x32).
// Register-prefetch software pipeline over the K loop.
// MODE 0: A=g_xh, W per blockIdx.z -> g_q/g_k/g_v ([b,h,n,d], fp16)
// MODE 1: A=g_aoh, W=Wo -> f32 out + bias
// ---------------------------------------------------------------------------
template <int MODE>
__global__ __launch_bounds__(256) void gemm_h(
    const float* __restrict__ bo, float* __restrict__ Cout)
{
    __shared__ __align__(16) __half As[128][40];   // pitch 80B
    __shared__ __align__(16) __half Bs[32][136];   // pitch 272B

    const __half* A = (MODE == 0) ? g_xh : g_aoh;
    const __half* W = (MODE == 0) ? g_wh + blockIdx.z * (DMODEL * DMODEL)
                                  : g_wh + 3 * (DMODEL * DMODEL);

    const int m0 = blockIdx.y * 128;
    const int n0 = blockIdx.x * 128;
    const int tid = threadIdx.x;
    const int lane = tid & 31;
    const int wid = tid >> 5;
    const int gid = lane >> 2;
    const int tig = lane & 3;
    const int wm = (wid & 1) * 64;
    const int wn = (wid >> 1) * 32;

    // per-thread load coords
    const int ar = tid >> 2, ac = (tid & 3) * 8;    // A: rows ar, ar+64
    const int br = tid >> 4, bc = (tid & 15) * 8;   // B: rows br, br+16

    float acc[4][4][4] = {};

    // prologue: prefetch k0 = 0
    uint4 pa0 = *(const uint4*)&A[(m0 + ar) * DMODEL + ac];
    uint4 pa1 = *(const uint4*)&A[(m0 + ar + 64) * DMODEL + ac];
    uint4 pb0 = *(const uint4*)&W[br * DMODEL + n0 + bc];
    uint4 pb1 = *(const uint4*)&W[(br + 16) * DMODEL + n0 + bc];

    for (int k0 = 0; k0 < DMODEL; k0 += 32) {
        __syncthreads();
        *(uint4*)&As[ar][ac] = pa0;
        *(uint4*)&As[ar + 64][ac] = pa1;
        *(uint4*)&Bs[br][bc] = pb0;
        *(uint4*)&Bs[br + 16][bc] = pb1;
        __syncthreads();

        int k1 = k0 + 32;
        if (k1 < DMODEL) {
            pa0 = *(const uint4*)&A[(m0 + ar) * DMODEL + k1 + ac];
            pa1 = *(const uint4*)&A[(m0 + ar + 64) * DMODEL + k1 + ac];
            pb0 = *(const uint4*)&W[(k1 + br) * DMODEL + n0 + bc];
            pb1 = *(const uint4*)&W[(k1 + br + 16) * DMODEL + n0 + bc];
        }

#pragma unroll
        for (int kc = 0; kc < 2; kc++) {
            unsigned a[4][4];
#pragma unroll
            for (int mf = 0; mf < 4; mf++) {
                unsigned addr = smem_u32(&As[wm + mf * 16 + (lane & 15)]
                                            [kc * 16 + (lane >> 4) * 8]);
                ldsm4(a[mf][0], a[mf][1], a[mf][2], a[mf][3], addr);
            }
            unsigned bfr[2][4];
#pragma unroll
            for (int nf2 = 0; nf2 < 2; nf2++) {
                unsigned addr = smem_u32(&Bs[kc * 16 + (lane & 15)]
                                            [wn + nf2 * 16 + (lane >> 4) * 8]);
                ldsm4t(bfr[nf2][0], bfr[nf2][1], bfr[nf2][2], bfr[nf2][3], addr);
            }
#pragma unroll
            for (int mf = 0; mf < 4; mf++)
#pragma unroll
                for (int nf = 0; nf < 4; nf++)
                    mma16(acc[mf][nf], a[mf], &bfr[nf >> 1][(nf & 1) * 2]);
        }
    }

    // Epilogue
#pragma unroll
    for (int mf = 0; mf < 4; mf++) {
#pragma unroll
        for (int nf = 0; nf < 4; nf++) {
            int row0 = m0 + wm + mf * 16 + gid;
            int row1 = row0 + 8;
            int col = n0 + wn + nf * 8 + 2 * tig;
            if (MODE == 0) {
                __half* outp = (blockIdx.z == 0) ? g_q : (blockIdx.z == 1) ? g_k : g_v;
                int hh = col >> 6, dd = col & 63;
                {
                    int bN = row0 >> 11, nn = row0 & (NSEQ - 1);
                    *(unsigned*)&outp[((bN * NH + hh) * NSEQ + nn) * DHEAD + dd] =
                        packh2(acc[mf][nf][0], acc[mf][nf][1]);
                }
                {
                    int bN = row1 >> 11, nn = row1 & (NSEQ - 1);
                    *(unsigned*)&outp[((bN * NH + hh) * NSEQ + nn) * DHEAD + dd] =
                        packh2(acc[mf][nf][2], acc[mf][nf][3]);
                }
            } else {
                float2 bv = *(const float2*)&bo[col];
                *(float2*)&Cout[row0 * DMODEL + col] =
                    make_float2(acc[mf][nf][0] + bv.x, acc[mf][nf][1] + bv.y);
                *(float2*)&Cout[row1 * DMODEL + col] =
                    make_float2(acc[mf][nf][2] + bv.x, acc[mf][nf][3] + bv.y);
            }
        }
    }
}

// ---------------------------------------------------------------------------
// fp16 flash attention, rel-pos bias + post-softmax gate.
// Block 256 thr (8 warps), one (b,h,128-row q tile). Warp owns 16 rows.
// Register-prefetch pipeline on K/V tile loads; combined bias/gate LUT with
// packed clamp indices.
// ---------------------------------------------------------------------------
__global__ __launch_bounds__(256) void attn_h(
    const float* __restrict__ rel_pos, const float* __restrict__ c_emb)
{
    __shared__ __align__(16) __half Ks[64][72];  // pitch 144B
    __shared__ __align__(16) __half Vs[64][72];
    __shared__ float2 bg[132];                   // (bias*scale, gate)

    const int it = blockIdx.x;
    const int h  = blockIdx.y;
    const int b  = blockIdx.z;
    const int tid = threadIdx.x;
    const int lane = tid & 31;
    const int w = tid >> 5;
    const int gid = lane >> 2;
    const int tig = lane & 3;
    const int iloc = w * 16;

    for (int r = tid; r < 2 * PCLAMP + 1; r += 256)
        bg[r] = make_float2(__ldg(&rel_pos[r * NH + h]) * 0.125f,
                            __ldg(&c_emb[r * NH + h]));

    // Q strip -> A fragments, scale folded (0.125 exact in fp16)
    const __half* qg = g_q + ((size_t)(b * NH + h) * NSEQ + it * 128 + iloc) * DHEAD;
    const __half2 sc = __float2half2_rn(0.125f);
    unsigned qa[4][4];
#pragma unroll
    for (int kc = 0; kc < 4; kc++) {
        __half2 v0 = *(const __half2*)&qg[gid * DHEAD + kc * 16 + 2 * tig];
        __half2 v1 = *(const __half2*)&qg[(gid + 8) * DHEAD + kc * 16 + 2 * tig];
        __half2 v2 = *(const __half2*)&qg[gid * DHEAD + kc * 16 + 8 + 2 * tig];
        __half2 v3 = *(const __half2*)&qg[(gid + 8) * DHEAD + kc * 16 + 8 + 2 * tig];
        v0 = __hmul2(v0, sc); v1 = __hmul2(v1, sc);
        v2 = __hmul2(v2, sc); v3 = __hmul2(v3, sc);
        qa[kc][0] = *(unsigned*)&v0; qa[kc][1] = *(unsigned*)&v1;
        qa[kc][2] = *(unsigned*)&v2; qa[kc][3] = *(unsigned*)&v3;
    }

    const __half* kg = g_k + ((size_t)(b * NH + h) * NSEQ) * DHEAD;
    const __half* vg = g_v + ((size_t)(b * NH + h) * NSEQ) * DHEAD;

    float o[8][4] = {};
    float rm0 = -1e30f, rm1 = -1e30f, l0 = 0.f, l1 = 0.f;
    const int i0g = it * 128 + iloc + gid;
    const int i1g = i0g + 8;

    // load coords: 2 uint4 per array per thread
    const int lr = tid >> 3, lc = (tid & 7) * 8;

    uint4 pk0 = *(const uint4*)&kg[lr * DHEAD + lc];
    uint4 pk1 = *(const uint4*)&kg[(lr + 32) * DHEAD + lc];
    uint4 pv0 = *(const uint4*)&vg[lr * DHEAD + lc];
    uint4 pv1 = *(const uint4*)&vg[(lr + 32) * DHEAD + lc];

    for (int jt = 0; jt < NSEQ / 64; jt++) {
        __syncthreads();
        *(uint4*)&Ks[lr][lc] = pk0;
        *(uint4*)&Ks[lr + 32][lc] = pk1;
        *(uint4*)&Vs[lr][lc] = pv0;
        *(uint4*)&Vs[lr + 32][lc] = pv1;
        __syncthreads();

        if (jt + 1 < NSEQ / 64) {
            int base = (jt + 1) * 64;
            pk0 = *(const uint4*)&kg[(base + lr) * DHEAD + lc];
            pk1 = *(const uint4*)&kg[(base + lr + 32) * DHEAD + lc];
            pv0 = *(const uint4*)&vg[(base + lr) * DHEAD + lc];
            pv1 = *(const uint4*)&vg[(base + lr + 32) * DHEAD + lc];
        }

        // S = Qs @ K^T  (16x64 per warp)
        float s[8][4] = {};
#pragma unroll
        for (int kc = 0; kc < 4; kc++) {
#pragma unroll
            for (int nf2 = 0; nf2 < 4; nf2++) {
                unsigned bfr[4];
                unsigned addr = smem_u32(
                    &Ks[nf2 * 16 + ((lane >> 4) & 1) * 8 + (lane & 7)]
                       [kc * 16 + ((lane >> 3) & 1) * 8]);
                ldsm4(bfr[0], bfr[1], bfr[2], bfr[3], addr);
                mma16(s[nf2 * 2], qa[kc], bfr + 0);
                mma16(s[nf2 * 2 + 1], qa[kc], bfr + 2);
            }
        }

        // Clamp indices (packed once), bias, row max
        unsigned idxp[8];
        float rmax0 = -1e30f, rmax1 = -1e30f;
#pragma unroll
        for (int nf = 0; nf < 8; nf++) {
            int jb = jt * 64 + nf * 8 + 2 * tig;
            int d00 = min(max(jb - i0g, -PCLAMP), PCLAMP) + PCLAMP;
            int d01 = min(max(jb + 1 - i0g, -PCLAMP), PCLAMP) + PCLAMP;
            int d10 = min(max(jb - i1g, -PCLAMP), PCLAMP) + PCLAMP;
            int d11 = min(max(jb + 1 - i1g, -PCLAMP), PCLAMP) + PCLAMP;
            idxp[nf] = (unsigned)d00 | ((unsigned)d01 << 8) |
                       ((unsigned)d10 << 16) | ((unsigned)d11 << 24);
            s[nf][0] += bg[d00].x;
            s[nf][1] += bg[d01].x;
            s[nf][2] += bg[d10].x;
            s[nf][3] += bg[d11].x;
            rmax0 = fmaxf(rmax0, fmaxf(s[nf][0], s[nf][1]));
            rmax1 = fmaxf(rmax1, fmaxf(s[nf][2], s[nf][3]));
        }
#pragma unroll
        for (int ofs = 1; ofs < 4; ofs <<= 1) {
            rmax0 = fmaxf(rmax0, __shfl_xor_sync(0xffffffffu, rmax0, ofs));
            rmax1 = fmaxf(rmax1, __shfl_xor_sync(0xffffffffu, rmax1, ofs));
        }

        float mn0 = fmaxf(rm0, rmax0), mn1 = fmaxf(rm1, rmax1);
        float f0 = __expf(rm0 - mn0), f1 = __expf(rm1 - mn1);
        rm0 = mn0; rm1 = mn1;
        float rs0 = 0.f, rs1 = 0.f;
#pragma unroll
        for (int nf = 0; nf < 8; nf++) {
            s[nf][0] = __expf(s[nf][0] - mn0);
            s[nf][1] = __expf(s[nf][1] - mn0);
            s[nf][2] = __expf(s[nf][2] - mn1);
            s[nf][3] = __expf(s[nf][3] - mn1);
            rs0 += s[nf][0] + s[nf][1];
            rs1 += s[nf][2] + s[nf][3];
        }
#pragma unroll
        for (int ofs = 1; ofs < 4; ofs <<= 1) {
            rs0 += __shfl_xor_sync(0xffffffffu, rs0, ofs);
            rs1 += __shfl_xor_sync(0xffffffffu, rs1, ofs);
        }
        l0 = l0 * f0 + rs0;
        l1 = l1 * f1 + rs1;
#pragma unroll
        for (int nf = 0; nf < 8; nf++) {
            o[nf][0] *= f0; o[nf][1] *= f0;
            o[nf][2] *= f1; o[nf][3] *= f1;
        }

        // Gate via cached indices, then P C-frags -> A-frags, O += P @ V
#pragma unroll
        for (int nf = 0; nf < 8; nf++) {
            unsigned ip = idxp[nf];
            s[nf][0] *= bg[ip & 255].y;
            s[nf][1] *= bg[(ip >> 8) & 255].y;
            s[nf][2] *= bg[(ip >> 16) & 255].y;
            s[nf][3] *= bg[ip >> 24].y;
        }
#pragma unroll
        for (int kc2 = 0; kc2 < 4; kc2++) {
            unsigned a[4];
            a[0] = packh2(s[2 * kc2][0], s[2 * kc2][1]);
            a[1] = packh2(s[2 * kc2][2], s[2 * kc2][3]);
            a[2] = packh2(s[2 * kc2 + 1][0], s[2 * kc2 + 1][1]);
            a[3] = packh2(s[2 * kc2 + 1][2], s[2 * kc2 + 1][3]);
#pragma unroll
            for (int nf2 = 0; nf2 < 4; nf2++) {
                unsigned bfr[4];
                unsigned addr = smem_u32(&Vs[kc2 * 16 + (lane & 15)]
                                            [nf2 * 16 + (lane >> 4) * 8]);
                ldsm4t(bfr[0], bfr[1], bfr[2], bfr[3], addr);
                mma16(o[nf2 * 2], a, bfr + 0);
                mma16(o[nf2 * 2 + 1], a, bfr + 2);
            }
        }
    }

    // Epilogue: normalize, write fp16 [b, n, h*64+d]
    float inv0 = 1.0f / l0, inv1 = 1.0f / l1;
    __half* og = g_aoh + ((size_t)(b * NSEQ + it * 128 + iloc)) * DMODEL + h * DHEAD;
#pragma unroll
    for (int nf = 0; nf < 8; nf++) {
        int col = nf * 8 + 2 * tig;
        *(unsigned*)&og[gid * DMODEL + col] = packh2(o[nf][0] * inv0, o[nf][1] * inv0);
        *(unsigned*)&og[(gid + 8) * DMODEL + col] = packh2(o[nf][2] * inv1, o[nf][3] * inv1);
    }
}

// ---------------------------------------------------------------------------
// Launch
// ---------------------------------------------------------------------------
extern "C" void kernel_launch(void* const* d_in, const int* in_sizes, int n_in,
                              void* d_out, int out_size)
{
    const float* x       = (const float*)d_in[0];
    const float* Wq      = (const float*)d_in[1];
    const float* Wk      = (const float*)d_in[2];
    const float* Wv      = (const float*)d_in[3];
    const float* rel_pos = (const float*)d_in[4];
    const float* c_emb   = (const float*)d_in[5];
    const float* Wo      = (const float*)d_in[6];
    const float* bo      = (const float*)d_in[7];
    float* out = (float*)d_out;

    (void)in_sizes; (void)n_in; (void)out_size;

    cvt_kernel<<<768, 256>>>(x, Wq, Wk, Wv, Wo);

    dim3 gq(DMODEL / 128, (BB * NSEQ) / 128, 3);
    gemm_h<0><<<gq, 256>>>(nullptr, nullptr);

    dim3 ga(NSEQ / 128, NH, BB);
    attn_h<<<ga, 256>>>(rel_pos, c_emb);

    dim3 go(DMODEL / 128, (BB * NSEQ) / 128, 1);
    gemm_h<1><<<go, 256>>>(bo, out);
}

// round 14
// speedup vs baseline: 8.9258x; 1.2098x over previous
#include <cuda_runtime.h>
#include <cuda_fp16.h>
#include <cstdint>

#define BB 2
#define NSEQ 2048
#define DMODEL 512
#define NH 8
#define DHEAD 64
#define PCLAMP 64
#define LOG2E 1.4426950408889634f

// Device-global scratch (no allocation allowed)
__device__ __half g_xh[BB * NSEQ * DMODEL];
__device__ __half g_wh[4 * DMODEL * DMODEL];
__device__ __half g_q[BB * NH * NSEQ * DHEAD];
__device__ __half g_k[BB * NH * NSEQ * DHEAD];
__device__ __half g_v[BB * NH * NSEQ * DHEAD];
__device__ __half g_aoh[BB * NSEQ * DMODEL];

__device__ __forceinline__ unsigned smem_u32(const void* p) {
    return (unsigned)__cvta_generic_to_shared(p);
}
__device__ __forceinline__ void ldsm4(unsigned& r0, unsigned& r1, unsigned& r2,
                                      unsigned& r3, unsigned addr) {
    asm volatile("ldmatrix.sync.aligned.m8n8.x4.shared.b16 {%0,%1,%2,%3}, [%4];"
                 : "=r"(r0), "=r"(r1), "=r"(r2), "=r"(r3) : "r"(addr));
}
__device__ __forceinline__ void ldsm4t(unsigned& r0, unsigned& r1, unsigned& r2,
                                       unsigned& r3, unsigned addr) {
    asm volatile("ldmatrix.sync.aligned.m8n8.x4.trans.shared.b16 {%0,%1,%2,%3}, [%4];"
                 : "=r"(r0), "=r"(r1), "=r"(r2), "=r"(r3) : "r"(addr));
}
__device__ __forceinline__ void mma16(float* c, const unsigned* a, const unsigned* b) {
    asm volatile(
        "mma.sync.aligned.m16n8k16.row.col.f32.f16.f16.f32 "
        "{%0,%1,%2,%3}, {%4,%5,%6,%7}, {%8,%9}, {%0,%1,%2,%3};"
        : "+f"(c[0]), "+f"(c[1]), "+f"(c[2]), "+f"(c[3])
        : "r"(a[0]), "r"(a[1]), "r"(a[2]), "r"(a[3]), "r"(b[0]), "r"(b[1]));
}
__device__ __forceinline__ unsigned packh2(float lo, float hi) {
    __half2 h = __floats2half2_rn(lo, hi);
    return *(unsigned*)&h;
}
__device__ __forceinline__ float ex2(float x) {
    float r;
    asm("ex2.approx.f32 %0, %1;" : "=f"(r) : "f"(x));
    return r;
}
__device__ __forceinline__ void cp16(unsigned dst, const void* src) {
    asm volatile("cp.async.cg.shared.global [%0], [%1], 16;" :: "r"(dst), "l"(src));
}
#define CP_COMMIT() asm volatile("cp.async.commit_group;")
#define CP_WAIT(n)  asm volatile("cp.async.wait_group %0;" :: "n"(n))

// ---------------------------------------------------------------------------
// fp32 -> fp16 conversion of x and 4 weight matrices.
// ---------------------------------------------------------------------------
__global__ __launch_bounds__(256) void cvt_kernel(
    const float* __restrict__ x, const float* __restrict__ Wq,
    const float* __restrict__ Wk, const float* __restrict__ Wv,
    const float* __restrict__ Wo)
{
    int i = blockIdx.x * 256 + threadIdx.x;
#pragma unroll
    for (int t = 0; t < 4; t++, i += 196608) {
        const float* src;
        __half* dst;
        int off;
        if (i < 524288) { src = x; dst = g_xh; off = i; }
        else {
            int j = i - 524288;
            int w = j >> 16;
            off = j & 65535;
            src = (w == 0) ? Wq : (w == 1) ? Wk : (w == 2) ? Wv : Wo;
            dst = g_wh + w * (DMODEL * DMODEL);
        }
        float4 v = ((const float4*)src)[off];
        *(uint2*)&dst[off * 4] = make_uint2(packh2(v.x, v.y), packh2(v.z, v.w));
    }
}

// ---------------------------------------------------------------------------
// fp16 GEMM: C[4096x512] = A[4096x512] @ W[512x512]
// MODE 0: tile 128x128 (warp 64x32), A=g_xh, W per z -> g_q/g_k/g_v
// MODE 1: tile 128x64  (warp 32x32), A=g_aoh, W=Wo -> f32 out + bias
// Register-prefetch pipeline; forced 2 CTAs/SM.
// ---------------------------------------------------------------------------
template <int MODE>
__global__ __launch_bounds__(256, 2) void gemm_h(
    const float* __restrict__ bo, float* __restrict__ Cout)
{
    constexpr int TN = MODE ? 64 : 128;
    constexpr int MF = MODE ? 2 : 4;

    __shared__ __align__(16) __half As[128][40];   // pitch 80B
    __shared__ __align__(16) __half Bs[32][136];   // pitch 272B

    const __half* A = MODE ? g_aoh : g_xh;
    const __half* W = g_wh + (MODE ? 3 : blockIdx.z) * (DMODEL * DMODEL);

    const int m0 = blockIdx.y * 128;
    const int n0 = blockIdx.x * TN;
    const int tid = threadIdx.x;
    const int lane = tid & 31;
    const int wid = tid >> 5;
    const int gid = lane >> 2;
    const int tig = lane & 3;
    const int wm = MODE ? (wid & 3) * 32 : (wid & 1) * 64;
    const int wn = MODE ? (wid >> 2) * 32 : (wid >> 1) * 32;

    const int ar = tid >> 2, ac = (tid & 3) * 8;
    const int br0 = MODE ? (tid >> 3) : (tid >> 4);
    const int bc = MODE ? (tid & 7) * 8 : (tid & 15) * 8;

    float acc[MF][4][4] = {};

    uint4 pa0 = *(const uint4*)&A[(m0 + ar) * DMODEL + ac];
    uint4 pa1 = *(const uint4*)&A[(m0 + ar + 64) * DMODEL + ac];
    uint4 pb0 = *(const uint4*)&W[br0 * DMODEL + n0 + bc];
    uint4 pb1;
    if (!MODE) pb1 = *(const uint4*)&W[(br0 + 16) * DMODEL + n0 + bc];

    for (int k0 = 0; k0 < DMODEL; k0 += 32) {
        __syncthreads();
        *(uint4*)&As[ar][ac] = pa0;
        *(uint4*)&As[ar + 64][ac] = pa1;
        *(uint4*)&Bs[br0][bc] = pb0;
        if (!MODE) *(uint4*)&Bs[br0 + 16][bc] = pb1;
        __syncthreads();

        int k1 = k0 + 32;
        if (k1 < DMODEL) {
            pa0 = *(const uint4*)&A[(m0 + ar) * DMODEL + k1 + ac];
            pa1 = *(const uint4*)&A[(m0 + ar + 64) * DMODEL + k1 + ac];
            pb0 = *(const uint4*)&W[(k1 + br0) * DMODEL + n0 + bc];
            if (!MODE) pb1 = *(const uint4*)&W[(k1 + br0 + 16) * DMODEL + n0 + bc];
        }

#pragma unroll
        for (int kc = 0; kc < 2; kc++) {
            unsigned a[MF][4];
#pragma unroll
            for (int mf = 0; mf < MF; mf++) {
                unsigned addr = smem_u32(&As[wm + mf * 16 + (lane & 15)]
                                            [kc * 16 + (lane >> 4) * 8]);
                ldsm4(a[mf][0], a[mf][1], a[mf][2], a[mf][3], addr);
            }
            unsigned bfr[2][4];
#pragma unroll
            for (int nf2 = 0; nf2 < 2; nf2++) {
                unsigned addr = smem_u32(&Bs[kc * 16 + (lane & 15)]
                                            [wn + nf2 * 16 + (lane >> 4) * 8]);
                ldsm4t(bfr[nf2][0], bfr[nf2][1], bfr[nf2][2], bfr[nf2][3], addr);
            }
#pragma unroll
            for (int mf = 0; mf < MF; mf++)
#pragma unroll
                for (int nf = 0; nf < 4; nf++)
                    mma16(acc[mf][nf], a[mf], &bfr[nf >> 1][(nf & 1) * 2]);
        }
    }

    // Epilogue
#pragma unroll
    for (int mf = 0; mf < MF; mf++) {
#pragma unroll
        for (int nf = 0; nf < 4; nf++) {
            int row0 = m0 + wm + mf * 16 + gid;
            int row1 = row0 + 8;
            int col = n0 + wn + nf * 8 + 2 * tig;
            if (MODE == 0) {
                __half* outp = (blockIdx.z == 0) ? g_q : (blockIdx.z == 1) ? g_k : g_v;
                int hh = col >> 6, dd = col & 63;
                {
                    int bN = row0 >> 11, nn = row0 & (NSEQ - 1);
                    *(unsigned*)&outp[((bN * NH + hh) * NSEQ + nn) * DHEAD + dd] =
                        packh2(acc[mf][nf][0], acc[mf][nf][1]);
                }
                {
                    int bN = row1 >> 11, nn = row1 & (NSEQ - 1);
                    *(unsigned*)&outp[((bN * NH + hh) * NSEQ + nn) * DHEAD + dd] =
                        packh2(acc[mf][nf][2], acc[mf][nf][3]);
                }
            } else {
                float2 bv = *(const float2*)&bo[col];
                *(float2*)&Cout[row0 * DMODEL + col] =
                    make_float2(acc[mf][nf][0] + bv.x, acc[mf][nf][1] + bv.y);
                *(float2*)&Cout[row1 * DMODEL + col] =
                    make_float2(acc[mf][nf][2] + bv.x, acc[mf][nf][3] + bv.y);
            }
        }
    }
}

// ---------------------------------------------------------------------------
// fp16 flash attention. No-max softmax (scores analytically bounded << 80),
// deferred l-reduction, bias folded into single FFMA + ex2.approx,
// cp.async double-buffered K/V tiles. 256 thr, 128 q rows per block.
// ---------------------------------------------------------------------------
__global__ __launch_bounds__(256, 2) void attn_h(
    const float* __restrict__ rel_pos, const float* __restrict__ c_emb)
{
    __shared__ __align__(16) __half Ks[2][64][72];
    __shared__ __align__(16) __half Vs[2][64][72];
    __shared__ float2 bg[132];  // (bias*0.125*log2e, gate)

    const int it = blockIdx.x;
    const int h  = blockIdx.y;
    const int b  = blockIdx.z;
    const int tid = threadIdx.x;
    const int lane = tid & 31;
    const int w = tid >> 5;
    const int gid = lane >> 2;
    const int tig = lane & 3;
    const int iloc = w * 16;

    for (int r = tid; r < 2 * PCLAMP + 1; r += 256)
        bg[r] = make_float2(__ldg(&rel_pos[r * NH + h]) * (0.125f * LOG2E),
                            __ldg(&c_emb[r * NH + h]));

    // Q strip -> A fragments, scale 0.125 folded (exact in fp16)
    const __half* qg = g_q + ((size_t)(b * NH + h) * NSEQ + it * 128 + iloc) * DHEAD;
    const __half2 sc = __float2half2_rn(0.125f);
    unsigned qa[4][4];
#pragma unroll
    for (int kc = 0; kc < 4; kc++) {
        __half2 v0 = *(const __half2*)&qg[gid * DHEAD + kc * 16 + 2 * tig];
        __half2 v1 = *(const __half2*)&qg[(gid + 8) * DHEAD + kc * 16 + 2 * tig];
        __half2 v2 = *(const __half2*)&qg[gid * DHEAD + kc * 16 + 8 + 2 * tig];
        __half2 v3 = *(const __half2*)&qg[(gid + 8) * DHEAD + kc * 16 + 8 + 2 * tig];
        v0 = __hmul2(v0, sc); v1 = __hmul2(v1, sc);
        v2 = __hmul2(v2, sc); v3 = __hmul2(v3, sc);
        qa[kc][0] = *(unsigned*)&v0; qa[kc][1] = *(unsigned*)&v1;
        qa[kc][2] = *(unsigned*)&v2; qa[kc][3] = *(unsigned*)&v3;
    }

    const __half* kg = g_k + ((size_t)(b * NH + h) * NSEQ) * DHEAD;
    const __half* vg = g_v + ((size_t)(b * NH + h) * NSEQ) * DHEAD;

    const int lr = tid >> 3, lc = (tid & 7) * 8;
    const int NT = NSEQ / 64;

    // prologue: async-load tile 0 into buffer 0
    {
        cp16(smem_u32(&Ks[0][lr][lc]), &kg[lr * DHEAD + lc]);
        cp16(smem_u32(&Ks[0][lr + 32][lc]), &kg[(lr + 32) * DHEAD + lc]);
        cp16(smem_u32(&Vs[0][lr][lc]), &vg[lr * DHEAD + lc]);
        cp16(smem_u32(&Vs[0][lr + 32][lc]), &vg[(lr + 32) * DHEAD + lc]);
        CP_COMMIT();
    }

    float o[8][4] = {};
    float l0 = 0.f, l1 = 0.f;
    const int i0g = it * 128 + iloc + gid;
    const int i1g = i0g + 8;

    for (int jt = 0; jt < NT; jt++) {
        const int cur = jt & 1;
        if (jt + 1 < NT) {
            const int nxt = cur ^ 1;
            int base = (jt + 1) * 64;
            cp16(smem_u32(&Ks[nxt][lr][lc]), &kg[(base + lr) * DHEAD + lc]);
            cp16(smem_u32(&Ks[nxt][lr + 32][lc]), &kg[(base + lr + 32) * DHEAD + lc]);
            cp16(smem_u32(&Vs[nxt][lr][lc]), &vg[(base + lr) * DHEAD + lc]);
            cp16(smem_u32(&Vs[nxt][lr + 32][lc]), &vg[(base + lr + 32) * DHEAD + lc]);
            CP_COMMIT();
            CP_WAIT(1);
        } else {
            CP_WAIT(0);
        }
        __syncthreads();

        // S = Qs @ K^T  (16x64 per warp)
        float s[8][4] = {};
#pragma unroll
        for (int kc = 0; kc < 4; kc++) {
#pragma unroll
            for (int nf2 = 0; nf2 < 4; nf2++) {
                unsigned bfr[4];
                unsigned addr = smem_u32(
                    &Ks[cur][nf2 * 16 + ((lane >> 4) & 1) * 8 + (lane & 7)]
                            [kc * 16 + ((lane >> 3) & 1) * 8]);
                ldsm4(bfr[0], bfr[1], bfr[2], bfr[3], addr);
                mma16(s[nf2 * 2], qa[kc], bfr + 0);
                mma16(s[nf2 * 2 + 1], qa[kc], bfr + 2);
            }
        }

        // exp2(s*log2e + biasterm), accumulate l, apply gate -- no max needed
#pragma unroll
        for (int nf = 0; nf < 8; nf++) {
            int jb = jt * 64 + nf * 8 + 2 * tig;
            int d00 = min(max(jb - i0g, -PCLAMP), PCLAMP) + PCLAMP;
            int d01 = min(max(jb + 1 - i0g, -PCLAMP), PCLAMP) + PCLAMP;
            int d10 = min(max(jb - i1g, -PCLAMP), PCLAMP) + PCLAMP;
            int d11 = min(max(jb + 1 - i1g, -PCLAMP), PCLAMP) + PCLAMP;
            float2 g00 = bg[d00], g01 = bg[d01], g10 = bg[d10], g11 = bg[d11];
            float e0 = ex2(fmaf(s[nf][0], LOG2E, g00.x));
            float e1 = ex2(fmaf(s[nf][1], LOG2E, g01.x));
            float e2 = ex2(fmaf(s[nf][2], LOG2E, g10.x));
            float e3 = ex2(fmaf(s[nf][3], LOG2E, g11.x));
            l0 += e0 + e1;
            l1 += e2 + e3;
            s[nf][0] = e0 * g00.y;
            s[nf][1] = e1 * g01.y;
            s[nf][2] = e2 * g10.y;
            s[nf][3] = e3 * g11.y;
        }

        // P C-frags -> A-frags, O += P @ V
#pragma unroll
        for (int kc2 = 0; kc2 < 4; kc2++) {
            unsigned a[4];
            a[0] = packh2(s[2 * kc2][0], s[2 * kc2][1]);
            a[1] = packh2(s[2 * kc2][2], s[2 * kc2][3]);
            a[2] = packh2(s[2 * kc2 + 1][0], s[2 * kc2 + 1][1]);
            a[3] = packh2(s[2 * kc2 + 1][2], s[2 * kc2 + 1][3]);
#pragma unroll
            for (int nf2 = 0; nf2 < 4; nf2++) {
                unsigned bfr[4];
                unsigned addr = smem_u32(&Vs[cur][kc2 * 16 + (lane & 15)]
                                                 [nf2 * 16 + (lane >> 4) * 8]);
                ldsm4t(bfr[0], bfr[1], bfr[2], bfr[3], addr);
                mma16(o[nf2 * 2], a, bfr + 0);
                mma16(o[nf2 * 2 + 1], a, bfr + 2);
            }
        }
        __syncthreads();  // all warps done with buffer `cur` before overwrite
    }

    // Deferred l reduction across the 4 lanes of each row group
#pragma unroll
    for (int ofs = 1; ofs < 4; ofs <<= 1) {
        l0 += __shfl_xor_sync(0xffffffffu, l0, ofs);
        l1 += __shfl_xor_sync(0xffffffffu, l1, ofs);
    }

    float inv0 = 1.0f / l0, inv1 = 1.0f / l1;
    __half* og = g_aoh + ((size_t)(b * NSEQ + it * 128 + iloc)) * DMODEL + h * DHEAD;
#pragma unroll
    for (int nf = 0; nf < 8; nf++) {
        int col = nf * 8 + 2 * tig;
        *(unsigned*)&og[gid * DMODEL + col] = packh2(o[nf][0] * inv0, o[nf][1] * inv0);
        *(unsigned*)&og[(gid + 8) * DMODEL + col] = packh2(o[nf][2] * inv1, o[nf][3] * inv1);
    }
}

// ---------------------------------------------------------------------------
// Launch
// ---------------------------------------------------------------------------
extern "C" void kernel_launch(void* const* d_in, const int* in_sizes, int n_in,
                              void* d_out, int out_size)
{
    const float* x       = (const float*)d_in[0];
    const float* Wq      = (const float*)d_in[1];
    const float* Wk      = (const float*)d_in[2];
    const float* Wv      = (const float*)d_in[3];
    const float* rel_pos = (const float*)d_in[4];
    const float* c_emb   = (const float*)d_in[5];
    const float* Wo      = (const float*)d_in[6];
    const float* bo      = (const float*)d_in[7];
    float* out = (float*)d_out;

    (void)in_sizes; (void)n_in; (void)out_size;

    cvt_kernel<<<768, 256>>>(x, Wq, Wk, Wv, Wo);

    dim3 gq(DMODEL / 128, (BB * NSEQ) / 128, 3);
    gemm_h<0><<<gq, 256>>>(nullptr, nullptr);

    dim3 ga(NSEQ / 128, NH, BB);
    attn_h<<<ga, 256>>>(rel_pos, c_emb);

    dim3 go(DMODEL / 64, (BB * NSEQ) / 128, 1);
    gemm_h<1><<<go, 256>>>(bo, out);
}

// round 16
// speedup vs baseline: 9.3526x; 1.0478x over previous
#include <cuda_runtime.h>
#include <cuda_fp16.h>
#include <cstdint>

#define BB 2
#define NSEQ 2048
#define DMODEL 512
#define NH 8
#define DHEAD 64
#define PCLAMP 64
#define LOG2E 1.4426950408889634f

// Device-global scratch (no allocation allowed)
__device__ __half g_xh[BB * NSEQ * DMODEL];
__device__ __half g_wh[4 * DMODEL * DMODEL];
__device__ __half g_q[BB * NH * NSEQ * DHEAD];
__device__ __half g_k[BB * NH * NSEQ * DHEAD];
__device__ __half g_v[BB * NH * NSEQ * DHEAD];
__device__ __half g_aoh[BB * NSEQ * DMODEL];

__device__ __forceinline__ unsigned smem_u32(const void* p) {
    return (unsigned)__cvta_generic_to_shared(p);
}
__device__ __forceinline__ void ldsm4(unsigned& r0, unsigned& r1, unsigned& r2,
                                      unsigned& r3, unsigned addr) {
    asm volatile("ldmatrix.sync.aligned.m8n8.x4.shared.b16 {%0,%1,%2,%3}, [%4];"
                 : "=r"(r0), "=r"(r1), "=r"(r2), "=r"(r3) : "r"(addr));
}
__device__ __forceinline__ void ldsm4t(unsigned& r0, unsigned& r1, unsigned& r2,
                                       unsigned& r3, unsigned addr) {
    asm volatile("ldmatrix.sync.aligned.m8n8.x4.trans.shared.b16 {%0,%1,%2,%3}, [%4];"
                 : "=r"(r0), "=r"(r1), "=r"(r2), "=r"(r3) : "r"(addr));
}
__device__ __forceinline__ void mma16(float* c, const unsigned* a, const unsigned* b) {
    asm volatile(
        "mma.sync.aligned.m16n8k16.row.col.f32.f16.f16.f32 "
        "{%0,%1,%2,%3}, {%4,%5,%6,%7}, {%8,%9}, {%0,%1,%2,%3};"
        : "+f"(c[0]), "+f"(c[1]), "+f"(c[2]), "+f"(c[3])
        : "r"(a[0]), "r"(a[1]), "r"(a[2]), "r"(a[3]), "r"(b[0]), "r"(b[1]));
}
__device__ __forceinline__ unsigned packh2(float lo, float hi) {
    __half2 h = __floats2half2_rn(lo, hi);
    return *(unsigned*)&h;
}
__device__ __forceinline__ float ex2(float x) {
    float r;
    asm("ex2.approx.f32 %0, %1;" : "=f"(r) : "f"(x));
    return r;
}
__device__ __forceinline__ void cp16(unsigned dst, const void* src) {
    asm volatile("cp.async.cg.shared.global [%0], [%1], 16;" :: "r"(dst), "l"(src));
}
#define CP_COMMIT() asm volatile("cp.async.commit_group;")
#define CP_WAIT0()  asm volatile("cp.async.wait_group 0;")

// ---------------------------------------------------------------------------
// fp32 -> fp16 conversion of x and 4 weight matrices.
// ---------------------------------------------------------------------------
__global__ __launch_bounds__(256) void cvt_kernel(
    const float* __restrict__ x, const float* __restrict__ Wq,
    const float* __restrict__ Wk, const float* __restrict__ Wv,
    const float* __restrict__ Wo)
{
    int i = blockIdx.x * 256 + threadIdx.x;
#pragma unroll
    for (int t = 0; t < 4; t++, i += 196608) {
        const float* src;
        __half* dst;
        int off;
        if (i < 524288) { src = x; dst = g_xh; off = i; }
        else {
            int j = i - 524288;
            int w = j >> 16;
            off = j & 65535;
            src = (w == 0) ? Wq : (w == 1) ? Wk : (w == 2) ? Wv : Wo;
            dst = g_wh + w * (DMODEL * DMODEL);
        }
        float4 v = ((const float4*)src)[off];
        *(uint2*)&dst[off * 4] = make_uint2(packh2(v.x, v.y), packh2(v.z, v.w));
    }
}

// ---------------------------------------------------------------------------
// fp16 GEMM: C[4096x512] = A[4096x512] @ W[512x512]
// TM x 128 tile, BK=32, 256 thr (8 warps 2x4). cp.async double-buffered,
// single __syncthreads per K-step.
// MODE 0 (TM=128): A=g_xh, W per z -> g_q/g_k/g_v ([b,h,n,d], fp16)
// MODE 1 (TM=64):  A=g_aoh, W=Wo -> f32 out + bias
// ---------------------------------------------------------------------------
template <int TM, int MODE>
__global__ __launch_bounds__(256, 2) void gemm_h(
    const float* __restrict__ bo, float* __restrict__ Cout)
{
    constexpr int MF = TM / 32;  // m16 fragments per warp

    __shared__ __align__(16) __half As[2][TM][40];    // pitch 80B
    __shared__ __align__(16) __half Bs[2][32][136];   // pitch 272B

    const __half* A = MODE ? g_aoh : g_xh;
    const __half* W = g_wh + (MODE ? 3 : blockIdx.z) * (DMODEL * DMODEL);

    const int m0 = blockIdx.y * TM;
    const int n0 = blockIdx.x * 128;
    const int tid = threadIdx.x;
    const int lane = tid & 31;
    const int wid = tid >> 5;
    const int gid = lane >> 2;
    const int tig = lane & 3;
    const int wm = (wid & 1) * (TM / 2);
    const int wn = (wid >> 1) * 32;

    const int ar = tid >> 2, ac = (tid & 3) * 8;   // A: 4 chunks/row
    const int br = tid >> 4, bc = (tid & 15) * 8;  // B: 16 chunks/row

    float acc[MF][4][4] = {};

    // async stage loader
    auto issue = [&](int k0, int buf) {
        cp16(smem_u32(&As[buf][ar][ac]), &A[(m0 + ar) * DMODEL + k0 + ac]);
        if (TM == 128)
            cp16(smem_u32(&As[buf][ar + 64][ac]),
                 &A[(m0 + ar + 64) * DMODEL + k0 + ac]);
        cp16(smem_u32(&Bs[buf][br][bc]), &W[(k0 + br) * DMODEL + n0 + bc]);
        cp16(smem_u32(&Bs[buf][br + 16][bc]), &W[(k0 + br + 16) * DMODEL + n0 + bc]);
    };

    issue(0, 0);
    CP_COMMIT();

    for (int it = 0; it < DMODEL / 32; it++) {
        const int cur = it & 1;
        CP_WAIT0();
        __syncthreads();
        if (it + 1 < DMODEL / 32) {
            issue((it + 1) * 32, cur ^ 1);
            CP_COMMIT();
        }

#pragma unroll
        for (int kc = 0; kc < 2; kc++) {
            unsigned a[MF][4];
#pragma unroll
            for (int mf = 0; mf < MF; mf++) {
                unsigned addr = smem_u32(&As[cur][wm + mf * 16 + (lane & 15)]
                                                 [kc * 16 + (lane >> 4) * 8]);
                ldsm4(a[mf][0], a[mf][1], a[mf][2], a[mf][3], addr);
            }
            unsigned bfr[2][4];
#pragma unroll
            for (int nf2 = 0; nf2 < 2; nf2++) {
                unsigned addr = smem_u32(&Bs[cur][kc * 16 + (lane & 15)]
                                                 [wn + nf2 * 16 + (lane >> 4) * 8]);
                ldsm4t(bfr[nf2][0], bfr[nf2][1], bfr[nf2][2], bfr[nf2][3], addr);
            }
#pragma unroll
            for (int mf = 0; mf < MF; mf++)
#pragma unroll
                for (int nf = 0; nf < 4; nf++)
                    mma16(acc[mf][nf], a[mf], &bfr[nf >> 1][(nf & 1) * 2]);
        }
    }

    // Epilogue
#pragma unroll
    for (int mf = 0; mf < MF; mf++) {
#pragma unroll
        for (int nf = 0; nf < 4; nf++) {
            int row0 = m0 + wm + mf * 16 + gid;
            int row1 = row0 + 8;
            int col = n0 + wn + nf * 8 + 2 * tig;
            if (MODE == 0) {
                __half* outp = (blockIdx.z == 0) ? g_q : (blockIdx.z == 1) ? g_k : g_v;
                int hh = col >> 6, dd = col & 63;
                {
                    int bN = row0 >> 11, nn = row0 & (NSEQ - 1);
                    *(unsigned*)&outp[((bN * NH + hh) * NSEQ + nn) * DHEAD + dd] =
                        packh2(acc[mf][nf][0], acc[mf][nf][1]);
                }
                {
                    int bN = row1 >> 11, nn = row1 & (NSEQ - 1);
                    *(unsigned*)&outp[((bN * NH + hh) * NSEQ + nn) * DHEAD + dd] =
                        packh2(acc[mf][nf][2], acc[mf][nf][3]);
                }
            } else {
                float2 bv = *(const float2*)&bo[col];
                *(float2*)&Cout[row0 * DMODEL + col] =
                    make_float2(acc[mf][nf][0] + bv.x, acc[mf][nf][1] + bv.y);
                *(float2*)&Cout[row1 * DMODEL + col] =
                    make_float2(acc[mf][nf][2] + bv.x, acc[mf][nf][3] + bv.y);
            }
        }
    }
}

// ---------------------------------------------------------------------------
// fp16 flash attention. No-max softmax, clamp-saturation fast path (28/32
// tiles per warp have tile-constant bias+gate), cp.async double-buffered
// K/V with single sync per tile. 256 thr, 128 q rows per block.
// ---------------------------------------------------------------------------
__global__ __launch_bounds__(256, 2) void attn_h(
    const float* __restrict__ rel_pos, const float* __restrict__ c_emb)
{
    __shared__ __align__(16) __half Ks[2][64][72];
    __shared__ __align__(16) __half Vs[2][64][72];
    __shared__ float2 bg[132];  // (bias*0.125*log2e, gate)

    const int it = blockIdx.x;
    const int h  = blockIdx.y;
    const int b  = blockIdx.z;
    const int tid = threadIdx.x;
    const int lane = tid & 31;
    const int w = tid >> 5;
    const int gid = lane >> 2;
    const int tig = lane & 3;
    const int iloc = w * 16;

    for (int r = tid; r < 2 * PCLAMP + 1; r += 256)
        bg[r] = make_float2(__ldg(&rel_pos[r * NH + h]) * (0.125f * LOG2E),
                            __ldg(&c_emb[r * NH + h]));

    // Q strip -> A fragments, scale 0.125 folded (exact in fp16)
    const __half* qg = g_q + ((size_t)(b * NH + h) * NSEQ + it * 128 + iloc) * DHEAD;
    const __half2 sc = __float2half2_rn(0.125f);
    unsigned qa[4][4];
#pragma unroll
    for (int kc = 0; kc < 4; kc++) {
        __half2 v0 = *(const __half2*)&qg[gid * DHEAD + kc * 16 + 2 * tig];
        __half2 v1 = *(const __half2*)&qg[(gid + 8) * DHEAD + kc * 16 + 2 * tig];
        __half2 v2 = *(const __half2*)&qg[gid * DHEAD + kc * 16 + 8 + 2 * tig];
        __half2 v3 = *(const __half2*)&qg[(gid + 8) * DHEAD + kc * 16 + 8 + 2 * tig];
        v0 = __hmul2(v0, sc); v1 = __hmul2(v1, sc);
        v2 = __hmul2(v2, sc); v3 = __hmul2(v3, sc);
        qa[kc][0] = *(unsigned*)&v0; qa[kc][1] = *(unsigned*)&v1;
        qa[kc][2] = *(unsigned*)&v2; qa[kc][3] = *(unsigned*)&v3;
    }

    const __half* kg = g_k + ((size_t)(b * NH + h) * NSEQ) * DHEAD;
    const __half* vg = g_v + ((size_t)(b * NH + h) * NSEQ) * DHEAD;

    const int lr = tid >> 3, lc = (tid & 7) * 8;
    const int NT = NSEQ / 64;

    auto issue = [&](int jt, int buf) {
        int base = jt * 64;
        cp16(smem_u32(&Ks[buf][lr][lc]), &kg[(base + lr) * DHEAD + lc]);
        cp16(smem_u32(&Ks[buf][lr + 32][lc]), &kg[(base + lr + 32) * DHEAD + lc]);
        cp16(smem_u32(&Vs[buf][lr][lc]), &vg[(base + lr) * DHEAD + lc]);
        cp16(smem_u32(&Vs[buf][lr + 32][lc]), &vg[(base + lr + 32) * DHEAD + lc]);
    };

    issue(0, 0);
    CP_COMMIT();

    float o[8][4] = {};
    float l0 = 0.f, l1 = 0.f;
    const int base_i = it * 128 + iloc;
    const int i0g = base_i + gid;
    const int i1g = i0g + 8;

    for (int jt = 0; jt < NT; jt++) {
        const int cur = jt & 1;
        CP_WAIT0();
        __syncthreads();
        if (jt + 1 < NT) {
            issue(jt + 1, cur ^ 1);
            CP_COMMIT();
        }

        // S = Qs @ K^T  (16x64 per warp)
        float s[8][4] = {};
#pragma unroll
        for (int kc = 0; kc < 4; kc++) {
#pragma unroll
            for (int nf2 = 0; nf2 < 4; nf2++) {
                unsigned bfr[4];
                unsigned addr = smem_u32(
                    &Ks[cur][nf2 * 16 + ((lane >> 4) & 1) * 8 + (lane & 7)]
                            [kc * 16 + ((lane >> 3) & 1) * 8]);
                ldsm4(bfr[0], bfr[1], bfr[2], bfr[3], addr);
                mma16(s[nf2 * 2], qa[kc], bfr + 0);
                mma16(s[nf2 * 2 + 1], qa[kc], bfr + 2);
            }
        }

        // Softmax (no max needed; scores bounded). Fast path when the whole
        // warp-tile's rel index is saturated to one clamp end.
        const int hi_rel = jt * 64 + 63 - base_i;        // max(j - i) over warp tile
        const int lo_rel = jt * 64 - (base_i + 15);      // min(j - i)
        if (hi_rel <= -PCLAMP || lo_rel >= PCLAMP) {
            float2 gg = bg[(hi_rel <= -PCLAMP) ? 0 : 2 * PCLAMP];
#pragma unroll
            for (int nf = 0; nf < 8; nf++) {
                float e0 = ex2(fmaf(s[nf][0], LOG2E, gg.x));
                float e1 = ex2(fmaf(s[nf][1], LOG2E, gg.x));
                float e2 = ex2(fmaf(s[nf][2], LOG2E, gg.x));
                float e3 = ex2(fmaf(s[nf][3], LOG2E, gg.x));
                l0 += e0 + e1;
                l1 += e2 + e3;
                s[nf][0] = e0 * gg.y;
                s[nf][1] = e1 * gg.y;
                s[nf][2] = e2 * gg.y;
                s[nf][3] = e3 * gg.y;
            }
        } else {
#pragma unroll
            for (int nf = 0; nf < 8; nf++) {
                int jb = jt * 64 + nf * 8 + 2 * tig;
                int d00 = min(max(jb - i0g, -PCLAMP), PCLAMP) + PCLAMP;
                int d01 = min(max(jb + 1 - i0g, -PCLAMP), PCLAMP) + PCLAMP;
                int d10 = min(max(jb - i1g, -PCLAMP), PCLAMP) + PCLAMP;
                int d11 = min(max(jb + 1 - i1g, -PCLAMP), PCLAMP) + PCLAMP;
                float2 g00 = bg[d00], g01 = bg[d01], g10 = bg[d10], g11 = bg[d11];
                float e0 = ex2(fmaf(s[nf][0], LOG2E, g00.x));
                float e1 = ex2(fmaf(s[nf][1], LOG2E, g01.x));
                float e2 = ex2(fmaf(s[nf][2], LOG2E, g10.x));
                float e3 = ex2(fmaf(s[nf][3], LOG2E, g11.x));
                l0 += e0 + e1;
                l1 += e2 + e3;
                s[nf][0] = e0 * g00.y;
                s[nf][1] = e1 * g01.y;
                s[nf][2] = e2 * g10.y;
                s[nf][3] = e3 * g11.y;
            }
        }

        // P C-frags -> A-frags, O += P @ V
#pragma unroll
        for (int kc2 = 0; kc2 < 4; kc2++) {
            unsigned a[4];
            a[0] = packh2(s[2 * kc2][0], s[2 * kc2][1]);
            a[1] = packh2(s[2 * kc2][2], s[2 * kc2][3]);
            a[2] = packh2(s[2 * kc2 + 1][0], s[2 * kc2 + 1][1]);
            a[3] = packh2(s[2 * kc2 + 1][2], s[2 * kc2 + 1][3]);
#pragma unroll
            for (int nf2 = 0; nf2 < 4; nf2++) {
                unsigned bfr[4];
                unsigned addr = smem_u32(&Vs[cur][kc2 * 16 + (lane & 15)]
                                                 [nf2 * 16 + (lane >> 4) * 8]);
                ldsm4t(bfr[0], bfr[1], bfr[2], bfr[3], addr);
                mma16(o[nf2 * 2], a, bfr + 0);
                mma16(o[nf2 * 2 + 1], a, bfr + 2);
            }
        }
    }

    // Deferred l reduction across the 4 lanes of each row group
#pragma unroll
    for (int ofs = 1; ofs < 4; ofs <<= 1) {
        l0 += __shfl_xor_sync(0xffffffffu, l0, ofs);
        l1 += __shfl_xor_sync(0xffffffffu, l1, ofs);
    }

    float inv0 = 1.0f / l0, inv1 = 1.0f / l1;
    __half* og = g_aoh + ((size_t)(b * NSEQ + it * 128 + iloc)) * DMODEL + h * DHEAD;
#pragma unroll
    for (int nf = 0; nf < 8; nf++) {
        int col = nf * 8 + 2 * tig;
        *(unsigned*)&og[gid * DMODEL + col] = packh2(o[nf][0] * inv0, o[nf][1] * inv0);
        *(unsigned*)&og[(gid + 8) * DMODEL + col] = packh2(o[nf][2] * inv1, o[nf][3] * inv1);
    }
}

// ---------------------------------------------------------------------------
// Launch
// ---------------------------------------------------------------------------
extern "C" void kernel_launch(void* const* d_in, const int* in_sizes, int n_in,
                              void* d_out, int out_size)
{
    const float* x       = (const float*)d_in[0];
    const float* Wq      = (const float*)d_in[1];
    const float* Wk      = (const float*)d_in[2];
    const float* Wv      = (const float*)d_in[3];
    const float* rel_pos = (const float*)d_in[4];
    const float* c_emb   = (const float*)d_in[5];
    const float* Wo      = (const float*)d_in[6];
    const float* bo      = (const float*)d_in[7];
    float* out = (float*)d_out;

    (void)in_sizes; (void)n_in; (void)out_size;

    cvt_kernel<<<768, 256>>>(x, Wq, Wk, Wv, Wo);

    dim3 gq(DMODEL / 128, (BB * NSEQ) / 128, 3);
    gemm_h<128, 0><<<gq, 256>>>(nullptr, nullptr);

    dim3 ga(NSEQ / 128, NH, BB);
    attn_h<<<ga, 256>>>(rel_pos, c_emb);

    dim3 go(DMODEL / 128, (BB * NSEQ) / 64, 1);
    gemm_h<64, 1><<<go, 256>>>(bo, out);
}

// round 17
// speedup vs baseline: 9.5283x; 1.0188x over previous
#include <cuda_runtime.h>
#include <cuda_fp16.h>
#include <cstdint>

#define BB 2
#define NSEQ 2048
#define DMODEL 512
#define NH 8
#define DHEAD 64
#define PCLAMP 64
#define LOG2E 1.4426950408889634f

// Device-global scratch (no allocation allowed)
__device__ __half g_xh[BB * NSEQ * DMODEL];
__device__ __half g_wh[4 * DMODEL * DMODEL];
__device__ __half g_q[BB * NH * NSEQ * DHEAD];
__device__ __half g_k[BB * NH * NSEQ * DHEAD];
__device__ __half g_v[BB * NH * NSEQ * DHEAD];
__device__ __half g_aoh[BB * NSEQ * DMODEL];

__device__ __forceinline__ unsigned smem_u32(const void* p) {
    return (unsigned)__cvta_generic_to_shared(p);
}
__device__ __forceinline__ void ldsm4(unsigned& r0, unsigned& r1, unsigned& r2,
                                      unsigned& r3, unsigned addr) {
    asm volatile("ldmatrix.sync.aligned.m8n8.x4.shared.b16 {%0,%1,%2,%3}, [%4];"
                 : "=r"(r0), "=r"(r1), "=r"(r2), "=r"(r3) : "r"(addr));
}
__device__ __forceinline__ void ldsm4t(unsigned& r0, unsigned& r1, unsigned& r2,
                                       unsigned& r3, unsigned addr) {
    asm volatile("ldmatrix.sync.aligned.m8n8.x4.trans.shared.b16 {%0,%1,%2,%3}, [%4];"
                 : "=r"(r0), "=r"(r1), "=r"(r2), "=r"(r3) : "r"(addr));
}
__device__ __forceinline__ void mma16(float* c, const unsigned* a, const unsigned* b) {
    asm volatile(
        "mma.sync.aligned.m16n8k16.row.col.f32.f16.f16.f32 "
        "{%0,%1,%2,%3}, {%4,%5,%6,%7}, {%8,%9}, {%0,%1,%2,%3};"
        : "+f"(c[0]), "+f"(c[1]), "+f"(c[2]), "+f"(c[3])
        : "r"(a[0]), "r"(a[1]), "r"(a[2]), "r"(a[3]), "r"(b[0]), "r"(b[1]));
}
__device__ __forceinline__ unsigned packh2(float lo, float hi) {
    __half2 h = __floats2half2_rn(lo, hi);
    return *(unsigned*)&h;
}
__device__ __forceinline__ float ex2(float x) {
    float r;
    asm("ex2.approx.f32 %0, %1;" : "=f"(r) : "f"(x));
    return r;
}
__device__ __forceinline__ void cp16(unsigned dst, const void* src) {
    asm volatile("cp.async.cg.shared.global [%0], [%1], 16;" :: "r"(dst), "l"(src));
}
#define CP_COMMIT() asm volatile("cp.async.commit_group;")
#define CP_WAIT(n)  asm volatile("cp.async.wait_group %0;" :: "n"(n))

// ---------------------------------------------------------------------------
// fp32 -> fp16 conversion of x and 4 weight matrices.
// ---------------------------------------------------------------------------
__global__ __launch_bounds__(256) void cvt_kernel(
    const float* __restrict__ x, const float* __restrict__ Wq,
    const float* __restrict__ Wk, const float* __restrict__ Wv,
    const float* __restrict__ Wo)
{
    int i = blockIdx.x * 256 + threadIdx.x;
#pragma unroll
    for (int t = 0; t < 4; t++, i += 196608) {
        const float* src;
        __half* dst;
        int off;
        if (i < 524288) { src = x; dst = g_xh; off = i; }
        else {
            int j = i - 524288;
            int w = j >> 16;
            off = j & 65535;
            src = (w == 0) ? Wq : (w == 1) ? Wk : (w == 2) ? Wv : Wo;
            dst = g_wh + w * (DMODEL * DMODEL);
        }
        float4 v = ((const float4*)src)[off];
        *(uint2*)&dst[off * 4] = make_uint2(packh2(v.x, v.y), packh2(v.z, v.w));
    }
}

// ---------------------------------------------------------------------------
// fp16 GEMM: C[4096x512] = A[4096x512] @ W[512x512]
// TM x 128 tile, BK=32, 256 thr (8 warps 2x4). 4-stage cp.async ring,
// wait_group<=2 (~2-3 compute phases of latency cover). Dynamic SMEM.
// MODE 0 (TM=128): A=g_xh, W per z -> g_q/g_k/g_v ([b,h,n,d], fp16)
// MODE 1 (TM=64):  A=g_aoh, W=Wo -> f32 out + bias
// ---------------------------------------------------------------------------
template <int TM, int MODE>
__global__ __launch_bounds__(256, 2) void gemm_h(
    const float* __restrict__ bo, float* __restrict__ Cout)
{
    constexpr int MF = TM / 32;
    constexpr int NS = 4;                 // pipeline stages
    constexpr int NK = DMODEL / 32;       // 16 K-steps

    extern __shared__ __align__(16) char dynsm[];
    typedef __half AsT[TM][40];           // pitch 80B
    typedef __half BsT[32][136];          // pitch 272B
    AsT* As = (AsT*)dynsm;
    BsT* Bs = (BsT*)(dynsm + NS * sizeof(AsT));

    const __half* A = MODE ? g_aoh : g_xh;
    const __half* W = g_wh + (MODE ? 3 : blockIdx.z) * (DMODEL * DMODEL);

    const int m0 = blockIdx.y * TM;
    const int n0 = blockIdx.x * 128;
    const int tid = threadIdx.x;
    const int lane = tid & 31;
    const int wid = tid >> 5;
    const int gid = lane >> 2;
    const int tig = lane & 3;
    const int wm = (wid & 1) * (TM / 2);
    const int wn = (wid >> 1) * 32;

    const int ar = tid >> 2, ac = (tid & 3) * 8;
    const int br = tid >> 4, bc = (tid & 15) * 8;

    float acc[MF][4][4] = {};

    auto issue = [&](int ks, int buf) {
        int k0 = ks * 32;
        cp16(smem_u32(&As[buf][ar][ac]), &A[(m0 + ar) * DMODEL + k0 + ac]);
        if (TM == 128)
            cp16(smem_u32(&As[buf][ar + 64][ac]),
                 &A[(m0 + ar + 64) * DMODEL + k0 + ac]);
        cp16(smem_u32(&Bs[buf][br][bc]), &W[(k0 + br) * DMODEL + n0 + bc]);
        cp16(smem_u32(&Bs[buf][br + 16][bc]), &W[(k0 + br + 16) * DMODEL + n0 + bc]);
        CP_COMMIT();
    };

    issue(0, 0);
    issue(1, 1);
    issue(2, 2);

    for (int it = 0; it < NK; it++) {
        const int cur = it & (NS - 1);
        CP_WAIT(2);          // 3 outstanding -> oldest (cur) complete
        __syncthreads();
        // clamped issue keeps group count uniform; dummy re-loads of the last
        // tile land in buffers never read again (sync-protected).
        issue(min(it + 3, NK - 1), (it + 3) & (NS - 1));

#pragma unroll
        for (int kc = 0; kc < 2; kc++) {
            unsigned a[MF][4];
#pragma unroll
            for (int mf = 0; mf < MF; mf++) {
                unsigned addr = smem_u32(&As[cur][wm + mf * 16 + (lane & 15)]
                                                 [kc * 16 + (lane >> 4) * 8]);
                ldsm4(a[mf][0], a[mf][1], a[mf][2], a[mf][3], addr);
            }
            unsigned bfr[2][4];
#pragma unroll
            for (int nf2 = 0; nf2 < 2; nf2++) {
                unsigned addr = smem_u32(&Bs[cur][kc * 16 + (lane & 15)]
                                                 [wn + nf2 * 16 + (lane >> 4) * 8]);
                ldsm4t(bfr[nf2][0], bfr[nf2][1], bfr[nf2][2], bfr[nf2][3], addr);
            }
#pragma unroll
            for (int mf = 0; mf < MF; mf++)
#pragma unroll
                for (int nf = 0; nf < 4; nf++)
                    mma16(acc[mf][nf], a[mf], &bfr[nf >> 1][(nf & 1) * 2]);
        }
    }

    // Epilogue
#pragma unroll
    for (int mf = 0; mf < MF; mf++) {
#pragma unroll
        for (int nf = 0; nf < 4; nf++) {
            int row0 = m0 + wm + mf * 16 + gid;
            int row1 = row0 + 8;
            int col = n0 + wn + nf * 8 + 2 * tig;
            if (MODE == 0) {
                __half* outp = (blockIdx.z == 0) ? g_q : (blockIdx.z == 1) ? g_k : g_v;
                int hh = col >> 6, dd = col & 63;
                {
                    int bN = row0 >> 11, nn = row0 & (NSEQ - 1);
                    *(unsigned*)&outp[((bN * NH + hh) * NSEQ + nn) * DHEAD + dd] =
                        packh2(acc[mf][nf][0], acc[mf][nf][1]);
                }
                {
                    int bN = row1 >> 11, nn = row1 & (NSEQ - 1);
                    *(unsigned*)&outp[((bN * NH + hh) * NSEQ + nn) * DHEAD + dd] =
                        packh2(acc[mf][nf][2], acc[mf][nf][3]);
                }
            } else {
                float2 bv = *(const float2*)&bo[col];
                *(float2*)&Cout[row0 * DMODEL + col] =
                    make_float2(acc[mf][nf][0] + bv.x, acc[mf][nf][1] + bv.y);
                *(float2*)&Cout[row1 * DMODEL + col] =
                    make_float2(acc[mf][nf][2] + bv.x, acc[mf][nf][3] + bv.y);
            }
        }
    }
}

// ---------------------------------------------------------------------------
// fp16 flash attention. No-max softmax, clamp-saturation fast path,
// 3-stage cp.async K/V ring (wait_group<=1). 256 thr, 128 q rows per block.
// Dynamic SMEM.
// ---------------------------------------------------------------------------
__global__ __launch_bounds__(256, 2) void attn_h(
    const float* __restrict__ rel_pos, const float* __restrict__ c_emb)
{
    constexpr int NS = 3;
    constexpr int NT = NSEQ / 64;

    extern __shared__ __align__(16) char dynsm[];
    typedef __half TileT[64][72];         // pitch 144B
    TileT* Ks = (TileT*)dynsm;
    TileT* Vs = (TileT*)(dynsm + NS * sizeof(TileT));
    __shared__ float2 bg[132];            // (bias*0.125*log2e, gate)

    const int it = blockIdx.x;
    const int h  = blockIdx.y;
    const int b  = blockIdx.z;
    const int tid = threadIdx.x;
    const int lane = tid & 31;
    const int w = tid >> 5;
    const int gid = lane >> 2;
    const int tig = lane & 3;
    const int iloc = w * 16;

    for (int r = tid; r < 2 * PCLAMP + 1; r += 256)
        bg[r] = make_float2(__ldg(&rel_pos[r * NH + h]) * (0.125f * LOG2E),
                            __ldg(&c_emb[r * NH + h]));

    // Q strip -> A fragments, scale 0.125 folded (exact in fp16)
    const __half* qg = g_q + ((size_t)(b * NH + h) * NSEQ + it * 128 + iloc) * DHEAD;
    const __half2 sc = __float2half2_rn(0.125f);
    unsigned qa[4][4];
#pragma unroll
    for (int kc = 0; kc < 4; kc++) {
        __half2 v0 = *(const __half2*)&qg[gid * DHEAD + kc * 16 + 2 * tig];
        __half2 v1 = *(const __half2*)&qg[(gid + 8) * DHEAD + kc * 16 + 2 * tig];
        __half2 v2 = *(const __half2*)&qg[gid * DHEAD + kc * 16 + 8 + 2 * tig];
        __half2 v3 = *(const __half2*)&qg[(gid + 8) * DHEAD + kc * 16 + 8 + 2 * tig];
        v0 = __hmul2(v0, sc); v1 = __hmul2(v1, sc);
        v2 = __hmul2(v2, sc); v3 = __hmul2(v3, sc);
        qa[kc][0] = *(unsigned*)&v0; qa[kc][1] = *(unsigned*)&v1;
        qa[kc][2] = *(unsigned*)&v2; qa[kc][3] = *(unsigned*)&v3;
    }

    const __half* kg = g_k + ((size_t)(b * NH + h) * NSEQ) * DHEAD;
    const __half* vg = g_v + ((size_t)(b * NH + h) * NSEQ) * DHEAD;

    const int lr = tid >> 3, lc = (tid & 7) * 8;

    auto issue = [&](int jt, int buf) {
        int base = jt * 64;
        cp16(smem_u32(&Ks[buf][lr][lc]), &kg[(base + lr) * DHEAD + lc]);
        cp16(smem_u32(&Ks[buf][lr + 32][lc]), &kg[(base + lr + 32) * DHEAD + lc]);
        cp16(smem_u32(&Vs[buf][lr][lc]), &vg[(base + lr) * DHEAD + lc]);
        cp16(smem_u32(&Vs[buf][lr + 32][lc]), &vg[(base + lr + 32) * DHEAD + lc]);
        CP_COMMIT();
    };

    issue(0, 0);
    issue(1, 1);

    float o[8][4] = {};
    float l0 = 0.f, l1 = 0.f;
    const int base_i = it * 128 + iloc;
    const int i0g = base_i + gid;
    const int i1g = i0g + 8;

    int cur = 0;
    for (int jt = 0; jt < NT; jt++) {
        CP_WAIT(1);          // 2 outstanding -> oldest (cur) complete
        __syncthreads();
        {
            int nj = min(jt + 2, NT - 1);
            int nb = cur + 2;
            if (nb >= NS) nb -= NS;
            issue(nj, nb);   // clamped dummy at tail (buffer sync-protected)
        }

        // S = Qs @ K^T  (16x64 per warp)
        float s[8][4] = {};
#pragma unroll
        for (int kc = 0; kc < 4; kc++) {
#pragma unroll
            for (int nf2 = 0; nf2 < 4; nf2++) {
                unsigned bfr[4];
                unsigned addr = smem_u32(
                    &Ks[cur][nf2 * 16 + ((lane >> 4) & 1) * 8 + (lane & 7)]
                            [kc * 16 + ((lane >> 3) & 1) * 8]);
                ldsm4(bfr[0], bfr[1], bfr[2], bfr[3], addr);
                mma16(s[nf2 * 2], qa[kc], bfr + 0);
                mma16(s[nf2 * 2 + 1], qa[kc], bfr + 2);
            }
        }

        // Softmax (no max; scores bounded). Saturation fast path.
        const int hi_rel = jt * 64 + 63 - base_i;
        const int lo_rel = jt * 64 - (base_i + 15);
        if (hi_rel <= -PCLAMP || lo_rel >= PCLAMP) {
            float2 gg = bg[(hi_rel <= -PCLAMP) ? 0 : 2 * PCLAMP];
#pragma unroll
            for (int nf = 0; nf < 8; nf++) {
                float e0 = ex2(fmaf(s[nf][0], LOG2E, gg.x));
                float e1 = ex2(fmaf(s[nf][1], LOG2E, gg.x));
                float e2 = ex2(fmaf(s[nf][2], LOG2E, gg.x));
                float e3 = ex2(fmaf(s[nf][3], LOG2E, gg.x));
                l0 += e0 + e1;
                l1 += e2 + e3;
                s[nf][0] = e0 * gg.y;
                s[nf][1] = e1 * gg.y;
                s[nf][2] = e2 * gg.y;
                s[nf][3] = e3 * gg.y;
            }
        } else {
#pragma unroll
            for (int nf = 0; nf < 8; nf++) {
                int jb = jt * 64 + nf * 8 + 2 * tig;
                int d00 = min(max(jb - i0g, -PCLAMP), PCLAMP) + PCLAMP;
                int d01 = min(max(jb + 1 - i0g, -PCLAMP), PCLAMP) + PCLAMP;
                int d10 = min(max(jb - i1g, -PCLAMP), PCLAMP) + PCLAMP;
                int d11 = min(max(jb + 1 - i1g, -PCLAMP), PCLAMP) + PCLAMP;
                float2 g00 = bg[d00], g01 = bg[d01], g10 = bg[d10], g11 = bg[d11];
                float e0 = ex2(fmaf(s[nf][0], LOG2E, g00.x));
                float e1 = ex2(fmaf(s[nf][1], LOG2E, g01.x));
                float e2 = ex2(fmaf(s[nf][2], LOG2E, g10.x));
                float e3 = ex2(fmaf(s[nf][3], LOG2E, g11.x));
                l0 += e0 + e1;
                l1 += e2 + e3;
                s[nf][0] = e0 * g00.y;
                s[nf][1] = e1 * g01.y;
                s[nf][2] = e2 * g10.y;
                s[nf][3] = e3 * g11.y;
            }
        }

        // P C-frags -> A-frags, O += P @ V
#pragma unroll
        for (int kc2 = 0; kc2 < 4; kc2++) {
            unsigned a[4];
            a[0] = packh2(s[2 * kc2][0], s[2 * kc2][1]);
            a[1] = packh2(s[2 * kc2][2], s[2 * kc2][3]);
            a[2] = packh2(s[2 * kc2 + 1][0], s[2 * kc2 + 1][1]);
            a[3] = packh2(s[2 * kc2 + 1][2], s[2 * kc2 + 1][3]);
#pragma unroll
            for (int nf2 = 0; nf2 < 4; nf2++) {
                unsigned bfr[4];
                unsigned addr = smem_u32(&Vs[cur][kc2 * 16 + (lane & 15)]
                                                 [nf2 * 16 + (lane >> 4) * 8]);
                ldsm4t(bfr[0], bfr[1], bfr[2], bfr[3], addr);
                mma16(o[nf2 * 2], a, bfr + 0);
                mma16(o[nf2 * 2 + 1], a, bfr + 2);
            }
        }
        if (++cur == NS) cur = 0;
    }

    // Deferred l reduction across the 4 lanes of each row group
#pragma unroll
    for (int ofs = 1; ofs < 4; ofs <<= 1) {
        l0 += __shfl_xor_sync(0xffffffffu, l0, ofs);
        l1 += __shfl_xor_sync(0xffffffffu, l1, ofs);
    }

    float inv0 = 1.0f / l0, inv1 = 1.0f / l1;
    __half* og = g_aoh + ((size_t)(b * NSEQ + it * 128 + iloc)) * DMODEL + h * DHEAD;
#pragma unroll
    for (int nf = 0; nf < 8; nf++) {
        int col = nf * 8 + 2 * tig;
        *(unsigned*)&og[gid * DMODEL + col] = packh2(o[nf][0] * inv0, o[nf][1] * inv0);
        *(unsigned*)&og[(gid + 8) * DMODEL + col] = packh2(o[nf][2] * inv1, o[nf][3] * inv1);
    }
}

// ---------------------------------------------------------------------------
// Launch
// ---------------------------------------------------------------------------
extern "C" void kernel_launch(void* const* d_in, const int* in_sizes, int n_in,
                              void* d_out, int out_size)
{
    const float* x       = (const float*)d_in[0];
    const float* Wq      = (const float*)d_in[1];
    const float* Wk      = (const float*)d_in[2];
    const float* Wv      = (const float*)d_in[3];
    const float* rel_pos = (const float*)d_in[4];
    const float* c_emb   = (const float*)d_in[5];
    const float* Wo      = (const float*)d_in[6];
    const float* bo      = (const float*)d_in[7];
    float* out = (float*)d_out;

    (void)in_sizes; (void)n_in; (void)out_size;

    // Dynamic SMEM sizes
    const int smem_g0 = 4 * (128 * 40 + 32 * 136) * 2;  // 75776
    const int smem_g1 = 4 * (64 * 40 + 32 * 136) * 2;   // 55296
    const int smem_at = 3 * (64 * 72) * 2 * 2;          // 55296

    cudaFuncSetAttribute(gemm_h<128, 0>,
                         cudaFuncAttributeMaxDynamicSharedMemorySize, smem_g0);
    cudaFuncSetAttribute(gemm_h<64, 1>,
                         cudaFuncAttributeMaxDynamicSharedMemorySize, smem_g1);
    cudaFuncSetAttribute(attn_h,
                         cudaFuncAttributeMaxDynamicSharedMemorySize, smem_at);

    cvt_kernel<<<768, 256>>>(x, Wq, Wk, Wv, Wo);

    dim3 gq(DMODEL / 128, (BB * NSEQ) / 128, 3);
    gemm_h<128, 0><<<gq, 256, smem_g0>>>(nullptr, nullptr);

    dim3 ga(NSEQ / 128, NH, BB);
    attn_h<<<ga, 256, smem_at>>>(rel_pos, c_emb);

    dim3 go(DMODEL / 128, (BB * NSEQ) / 64, 1);
    gemm_h<64, 1><<<go, 256, smem_g1>>>(bo, out);
}